// round 2
// baseline (speedup 1.0000x reference)
#include <cuda_runtime.h>

#define N_NODES 131072
#define N_EDGES 2097152
#define N_GRAPHS 64
#define NODES_PER_GRAPH 2048
#define D_IN 128
#define D_EMB 64
#define D_HID 128
#define N_ACT 2048

#define SCAN_BLOCKS 512           // 512 * 256 = 131072

// ---------------- scratch (device globals) -----------------------------------
__device__ float4 g_zl4 [N_NODES * D_EMB / 4];   // in @ Wl.T (messages)
__device__ float4 g_zr4 [N_NODES * D_EMB / 4];   // in @ Wr.T (self term)
__device__ float4 g_h4  [N_NODES * D_EMB / 4];   // h1 then h2
__device__ float  g_pool[N_GRAPHS * D_EMB];

__device__ int g_deg [N_NODES];
__device__ int g_off [N_NODES];
__device__ int g_cur [N_NODES];
__device__ int g_csr [N_EDGES];
__device__ int g_blksum[SCAN_BLOCKS];
__device__ int g_blkoff[SCAN_BLOCKS];

#define G_ZL  ((float*)g_zl4)
#define G_ZR  ((float*)g_zr4)
#define G_H   ((float*)g_h4)

// ================== CSR build (once per call, shared by both layers) =========
__global__ void deg_zero_kernel() {
    int i = blockIdx.x * blockDim.x + threadIdx.x;
    if (i < N_NODES) g_deg[i] = 0;
}

__global__ void hist_kernel(const int* __restrict__ dst) {
    int stride = gridDim.x * blockDim.x;
    for (int e = blockIdx.x * blockDim.x + threadIdx.x; e < N_EDGES; e += stride)
        atomicAdd(&g_deg[dst[e]], 1);
}

__global__ void blocksum_kernel() {          // SCAN_BLOCKS blocks x 256
    __shared__ int red[256];
    int i = blockIdx.x * 256 + threadIdx.x;
    red[threadIdx.x] = g_deg[i];
    __syncthreads();
    for (int s = 128; s > 0; s >>= 1) {
        if (threadIdx.x < s) red[threadIdx.x] += red[threadIdx.x + s];
        __syncthreads();
    }
    if (threadIdx.x == 0) g_blksum[blockIdx.x] = red[0];
}

__global__ void scan_blk_kernel() {          // 1 block x SCAN_BLOCKS threads
    __shared__ int sm[SCAN_BLOCKS];
    int t = threadIdx.x;
    sm[t] = g_blksum[t];
    __syncthreads();
    for (int d = 1; d < SCAN_BLOCKS; d <<= 1) {
        int v = (t >= d) ? sm[t - d] : 0;
        __syncthreads();
        sm[t] += v;
        __syncthreads();
    }
    g_blkoff[t] = sm[t] - g_blksum[t];       // exclusive
}

__global__ void offsets_kernel() {           // SCAN_BLOCKS blocks x 256
    __shared__ int sm[256];
    int i = blockIdx.x * 256 + threadIdx.x;
    int t = threadIdx.x;
    int d = g_deg[i];
    sm[t] = d;
    __syncthreads();
    for (int s = 1; s < 256; s <<= 1) {
        int v = (t >= s) ? sm[t - s] : 0;
        __syncthreads();
        sm[t] += v;
        __syncthreads();
    }
    int off = g_blkoff[blockIdx.x] + sm[t] - d;   // exclusive scan
    g_off[i] = off;
    g_cur[i] = off;
}

__global__ void scatter_kernel(const int* __restrict__ src,
                               const int* __restrict__ dst) {
    int stride = gridDim.x * blockDim.x;
    for (int e = blockIdx.x * blockDim.x + threadIdx.x; e < N_EDGES; e += stride) {
        int d = dst[e];
        int pos = atomicAdd(&g_cur[d], 1);
        g_csr[pos] = src[e];
    }
}

// ================== fused dual projection: zl = in@Wl.T, zr = in@Wr.T =========
// Block: 64 nodes x 128 outputs, 128 threads, 8x8 register micro-tile.
template <int K>
__global__ void lin_kernel(const float* __restrict__ in_param,
                           const float* __restrict__ Wl,
                           const float* __restrict__ Wr) {
    extern __shared__ float sm[];
    float* xs = sm;             // [64][K]
    float* Wt = sm + 64 * K;    // [K][128]  (outputs contiguous -> float4 loads)

    const float* in = (K == D_EMB) ? G_H : in_param;   // layer 2 reads h1

    const int tid = threadIdx.x;
    const int n0  = blockIdx.x * 64;

    // Stage weights transposed: Wt[k][o] (o<64 -> Wl, o>=64 -> Wr)
    for (int idx = tid; idx < 64 * K; idx += 128) {
        int o = idx / K, k = idx % K;                  // coalesced over k
        Wt[k * 128 + o]      = Wl[idx];
        Wt[k * 128 + 64 + o] = Wr[idx];
    }
    // Stage 64 input rows
    const float4* inv = (const float4*)(in + (size_t)n0 * K);
    float4* xsv = (float4*)xs;
    for (int idx = tid; idx < 64 * K / 4; idx += 128) xsv[idx] = inv[idx];
    __syncthreads();

    const int nr = tid >> 4;      // 0..7  (node group; nodes nr + 8a)
    const int tc = tid & 15;      // 0..15 (outputs tc*8 .. tc*8+7)

    float acc[8][8];
#pragma unroll
    for (int a = 0; a < 8; a++)
#pragma unroll
        for (int b = 0; b < 8; b++) acc[a][b] = 0.f;

#pragma unroll 2
    for (int k = 0; k < K; k++) {
        float xv[8];
#pragma unroll
        for (int a = 0; a < 8; a++) xv[a] = xs[(nr + 8 * a) * K + k];  // broadcast
        float4 w0 = *(const float4*)&Wt[k * 128 + tc * 8];
        float4 w1 = *(const float4*)&Wt[k * 128 + tc * 8 + 4];
#pragma unroll
        for (int a = 0; a < 8; a++) {
            acc[a][0] += xv[a] * w0.x;  acc[a][1] += xv[a] * w0.y;
            acc[a][2] += xv[a] * w0.z;  acc[a][3] += xv[a] * w0.w;
            acc[a][4] += xv[a] * w1.x;  acc[a][5] += xv[a] * w1.y;
            acc[a][6] += xv[a] * w1.z;  acc[a][7] += xv[a] * w1.w;
        }
    }

    float* base = (tc < 8) ? (G_ZL + tc * 8) : (G_ZR + (tc - 8) * 8);
#pragma unroll
    for (int a = 0; a < 8; a++) {
        size_t n = (size_t)(n0 + nr + 8 * a);
        float4* p = (float4*)(base + n * D_EMB);
        p[0] = make_float4(acc[a][0], acc[a][1], acc[a][2], acc[a][3]);
        p[1] = make_float4(acc[a][4], acc[a][5], acc[a][6], acc[a][7]);
    }
}

// ================== fused gather-aggregate + epilogue =========================
// One warp per node; lane handles 2 consecutive dims (float2).
// h[n] = (sum_{s in N(n)} zl[s]) / max(deg,1) + b + zr[n]
__global__ void gather_h_kernel(const float* __restrict__ b) {
    const int lane = threadIdx.x & 31;
    const int node = blockIdx.x * 8 + (threadIdx.x >> 5);
    if (node >= N_NODES) return;

    const int beg = g_off[node];
    const int deg = g_deg[node];
    const int end = beg + deg;

    const float2* zl2 = (const float2*)G_ZL;
    float2 s = make_float2(0.f, 0.f);

    int j = beg;
    for (; j + 4 <= end; j += 4) {
        int i0 = g_csr[j], i1 = g_csr[j + 1], i2 = g_csr[j + 2], i3 = g_csr[j + 3];
        float2 v0 = __ldg(&zl2[i0 * 32 + lane]);
        float2 v1 = __ldg(&zl2[i1 * 32 + lane]);
        float2 v2 = __ldg(&zl2[i2 * 32 + lane]);
        float2 v3 = __ldg(&zl2[i3 * 32 + lane]);
        s.x += (v0.x + v1.x) + (v2.x + v3.x);
        s.y += (v0.y + v1.y) + (v2.y + v3.y);
    }
    for (; j < end; j++) {
        float2 v = __ldg(&zl2[g_csr[j] * 32 + lane]);
        s.x += v.x; s.y += v.y;
    }

    const float inv = 1.0f / (float)max(deg, 1);
    const float2 zr = ((const float2*)G_ZR)[node * 32 + lane];
    float2 h;
    h.x = s.x * inv + __ldg(&b[lane * 2])     + zr.x;
    h.y = s.y * inv + __ldg(&b[lane * 2 + 1]) + zr.y;
    ((float2*)G_H)[node * 32 + lane] = h;
}

// ================== graph mean pool ==========================================
__global__ void pool_kernel() {
    __shared__ float red[256];
    const int g = blockIdx.x, tid = threadIdx.x;
    const int d = tid & 63, part = tid >> 6;
    const float* base = G_H + (size_t)g * NODES_PER_GRAPH * D_EMB;
    float s = 0.f;
    for (int n = part; n < NODES_PER_GRAPH; n += 4)
        s += base[n * D_EMB + d];
    red[tid] = s;
    __syncthreads();
    if (part == 0) {
        float t = red[d] + red[64 + d] + red[128 + d] + red[192 + d];
        g_pool[g * D_EMB + d] = t * (1.0f / NODES_PER_GRAPH);
    }
}

// ================== MLP head =================================================
__global__ void head_kernel(const float* __restrict__ fc1_W,
                            const float* __restrict__ fc1_b,
                            const float* __restrict__ fc2_W,
                            const float* __restrict__ fc2_b,
                            float* __restrict__ out) {
    __shared__ float gs[D_EMB];
    __shared__ float hs[D_HID];
    const int g = blockIdx.x, tid = threadIdx.x;
    if (tid < D_EMB) gs[tid] = g_pool[g * D_EMB + tid];
    __syncthreads();
    if (tid < D_HID) {
        float acc = fc1_b[tid];
        const float* w = fc1_W + (size_t)tid * D_EMB;
#pragma unroll
        for (int k = 0; k < D_EMB; k++) acc += gs[k] * w[k];
        hs[tid] = fmaxf(acc, 0.f);
    }
    __syncthreads();
    for (int a = tid; a < N_ACT; a += 256) {
        const float4* w = (const float4*)(fc2_W + (size_t)a * D_HID);
        float a0 = 0.f, a1 = 0.f, a2 = 0.f, a3 = 0.f;
#pragma unroll
        for (int k = 0; k < D_HID / 4; k++) {
            float4 wv = __ldg(&w[k]);
            a0 += wv.x * hs[4 * k + 0];
            a1 += wv.y * hs[4 * k + 1];
            a2 += wv.z * hs[4 * k + 2];
            a3 += wv.w * hs[4 * k + 3];
        }
        out[(size_t)g * N_ACT + a] = fc2_b[a] + (a0 + a1) + (a2 + a3);
    }
}

// ================== launch ===================================================
extern "C" void kernel_launch(void* const* d_in, const int* in_sizes, int n_in,
                              void* d_out, int out_size) {
    const float* x     = (const float*)d_in[0];
    const int*   ei    = (const int*)d_in[1];
    const float* W1l   = (const float*)d_in[2];
    const float* b1l   = (const float*)d_in[3];
    const float* W1r   = (const float*)d_in[4];
    const float* W2l   = (const float*)d_in[5];
    const float* b2l   = (const float*)d_in[6];
    const float* W2r   = (const float*)d_in[7];
    const float* fc1_W = (const float*)d_in[8];
    const float* fc1_b = (const float*)d_in[9];
    const float* fc2_W = (const float*)d_in[10];
    const float* fc2_b = (const float*)d_in[11];
    float* out = (float*)d_out;

    const int* src = ei;
    const int* dst = ei + N_EDGES;

    const int SMEM128 = (64 * D_IN + D_IN * 128) * 4;   // 98304 B
    const int SMEM64  = (64 * D_EMB + D_EMB * 128) * 4; // 49152 B
    cudaFuncSetAttribute(lin_kernel<D_IN>,  cudaFuncAttributeMaxDynamicSharedMemorySize, SMEM128);
    cudaFuncSetAttribute(lin_kernel<D_EMB>, cudaFuncAttributeMaxDynamicSharedMemorySize, SMEM64);

    // ---- CSR build (shared across both layers) ----
    deg_zero_kernel<<<N_NODES / 256, 256>>>();
    hist_kernel<<<2048, 256>>>(dst);
    blocksum_kernel<<<SCAN_BLOCKS, 256>>>();
    scan_blk_kernel<<<1, SCAN_BLOCKS>>>();
    offsets_kernel<<<SCAN_BLOCKS, 256>>>();
    scatter_kernel<<<2048, 256>>>(src, dst);

    // ---- layer 1 ----
    lin_kernel<D_IN><<<N_NODES / 64, 128, SMEM128>>>(x, W1l, W1r);
    gather_h_kernel<<<N_NODES / 8, 256>>>(b1l);

    // ---- layer 2 ----
    lin_kernel<D_EMB><<<N_NODES / 64, 128, SMEM64>>>(nullptr, W2l, W2r);
    gather_h_kernel<<<N_NODES / 8, 256>>>(b2l);

    // ---- pool + head ----
    pool_kernel<<<N_GRAPHS, 256>>>();
    head_kernel<<<N_GRAPHS, 256>>>(fc1_W, fc1_b, fc2_W, fc2_b, out);
}

// round 4
// speedup vs baseline: 1.0209x; 1.0209x over previous
#include <cuda_runtime.h>
#include <cstdint>

#define N_NODES 131072
#define N_EDGES 2097152
#define N_GRAPHS 64
#define NODES_PER_GRAPH 2048
#define D_IN 128
#define D_EMB 64
#define D_HID 128
#define N_ACT 2048

#define SCAN_BLOCKS 512           // 512 * 256 = 131072

// ---------------- scratch (device globals) -----------------------------------
__device__ float4 g_zl4 [N_NODES * D_EMB / 4];   // in @ Wl.T (messages)
__device__ float4 g_zr4 [N_NODES * D_EMB / 4];   // in @ Wr.T (self term)
__device__ float4 g_h4  [N_NODES * D_EMB / 4];   // h1 then h2
__device__ float  g_pool[N_GRAPHS * D_EMB];

__device__ int g_deg [N_NODES];
__device__ int g_off [N_NODES];
__device__ int g_cur [N_NODES];
__device__ int g_csr [N_EDGES];
__device__ int g_blksum[SCAN_BLOCKS];
__device__ int g_blkoff[SCAN_BLOCKS];

// pre-split tf32 weights, layout [n][k], n<64 -> Wl row, n>=64 -> Wr row
__device__ uint32_t g_w1hi[128 * 128];
__device__ uint32_t g_w1lo[128 * 128];
__device__ uint32_t g_w2hi[128 * 64];
__device__ uint32_t g_w2lo[128 * 64];

#define G_ZL  ((float*)g_zl4)
#define G_ZR  ((float*)g_zr4)
#define G_H   ((float*)g_h4)

// ---------------- tf32 helpers ------------------------------------------------
__device__ __forceinline__ void split_tf32(float v, uint32_t& hi, uint32_t& lo) {
    asm("cvt.rna.tf32.f32 %0, %1;" : "=r"(hi) : "f"(v));
    float r = v - __uint_as_float(hi);
    asm("cvt.rna.tf32.f32 %0, %1;" : "=r"(lo) : "f"(r));
}

#define MMA_TF32(C, a0, a1, a2, a3, b0, b1)                                   \
    asm volatile(                                                             \
        "mma.sync.aligned.m16n8k8.row.col.f32.tf32.tf32.f32 "                 \
        "{%0,%1,%2,%3}, {%4,%5,%6,%7}, {%8,%9}, {%0,%1,%2,%3};"               \
        : "+f"((C)[0]), "+f"((C)[1]), "+f"((C)[2]), "+f"((C)[3])              \
        : "r"(a0), "r"(a1), "r"(a2), "r"(a3), "r"(b0), "r"(b1))

// ================== CSR build =================================================
__global__ void deg_zero_kernel() {
    int i = blockIdx.x * blockDim.x + threadIdx.x;
    if (i < N_NODES) g_deg[i] = 0;
}

__global__ void hist_kernel(const int* __restrict__ dst) {
    int stride = gridDim.x * blockDim.x;
    for (int e = blockIdx.x * blockDim.x + threadIdx.x; e < N_EDGES; e += stride)
        atomicAdd(&g_deg[dst[e]], 1);
}

__global__ void blocksum_kernel() {
    __shared__ int red[256];
    int i = blockIdx.x * 256 + threadIdx.x;
    red[threadIdx.x] = g_deg[i];
    __syncthreads();
    for (int s = 128; s > 0; s >>= 1) {
        if (threadIdx.x < s) red[threadIdx.x] += red[threadIdx.x + s];
        __syncthreads();
    }
    if (threadIdx.x == 0) g_blksum[blockIdx.x] = red[0];
}

__global__ void scan_blk_kernel() {
    __shared__ int sm[SCAN_BLOCKS];
    int t = threadIdx.x;
    sm[t] = g_blksum[t];
    __syncthreads();
    for (int d = 1; d < SCAN_BLOCKS; d <<= 1) {
        int v = (t >= d) ? sm[t - d] : 0;
        __syncthreads();
        sm[t] += v;
        __syncthreads();
    }
    g_blkoff[t] = sm[t] - g_blksum[t];
}

__global__ void offsets_kernel() {
    __shared__ int sm[256];
    int i = blockIdx.x * 256 + threadIdx.x;
    int t = threadIdx.x;
    int d = g_deg[i];
    sm[t] = d;
    __syncthreads();
    for (int s = 1; s < 256; s <<= 1) {
        int v = (t >= s) ? sm[t - s] : 0;
        __syncthreads();
        sm[t] += v;
        __syncthreads();
    }
    int off = g_blkoff[blockIdx.x] + sm[t] - d;
    g_off[i] = off;
    g_cur[i] = off;
}

__global__ void scatter_kernel(const int* __restrict__ src,
                               const int* __restrict__ dst) {
    int stride = gridDim.x * blockDim.x;
    for (int e = blockIdx.x * blockDim.x + threadIdx.x; e < N_EDGES; e += stride) {
        int d = dst[e];
        int pos = atomicAdd(&g_cur[d], 1);
        g_csr[pos] = src[e];
    }
}

// ================== weight pre-split (once) ===================================
__global__ void wsplit_kernel(const float* __restrict__ W1l,
                              const float* __restrict__ W1r,
                              const float* __restrict__ W2l,
                              const float* __restrict__ W2r) {
    int i = blockIdx.x * blockDim.x + threadIdx.x;
    if (i < 128 * 128) {
        int n = i >> 7, k = i & 127;
        float v = (n < 64) ? W1l[n * 128 + k] : W1r[(n - 64) * 128 + k];
        uint32_t hi, lo;
        split_tf32(v, hi, lo);
        g_w1hi[i] = hi; g_w1lo[i] = lo;
    }
    if (i < 128 * 64) {
        int n = i >> 6, k = i & 63;
        float v = (n < 64) ? W2l[n * 64 + k] : W2r[(n - 64) * 64 + k];
        uint32_t hi, lo;
        split_tf32(v, hi, lo);
        g_w2hi[i] = hi; g_w2lo[i] = lo;
    }
}

// ================== tensor-core dual projection (3xTF32) ======================
// Block: 64 nodes x 128 outputs (64 -> zl, 64 -> zr), 128 threads = 4 warps.
// Warp w computes rows [w*16, w*16+16) x all 128 outputs via m16n8k8 mma.
// NOTE: weight symbols are resolved in DEVICE code (passing a __device__
// symbol from host code was the R3 crash).
template <int K>
__global__ void lin_tc_kernel(const float* __restrict__ in_param) {
    constexpr int SA = K + 4;        // A smem row stride (conflict-free frags)
    constexpr int SW = 136;          // W smem row stride
    extern __shared__ uint32_t sm[];
    uint32_t* As_hi = sm;                         // [64][SA]
    uint32_t* As_lo = As_hi + 64 * SA;
    uint32_t* Ws_hi = As_lo + 64 * SA;            // [K][SW]
    uint32_t* Ws_lo = Ws_hi + K * SW;

    const float*    in  = (K == D_EMB) ? G_H    : in_param;  // layer 2 reads h1
    const uint32_t* Whi = (K == D_EMB) ? g_w2hi : g_w1hi;
    const uint32_t* Wlo = (K == D_EMB) ? g_w2lo : g_w1lo;

    const int tid = threadIdx.x;
    const int node0 = blockIdx.x * 64;

    // Stage A (split into tf32 hi/lo), vectorized
    const float4* inv = (const float4*)(in + (size_t)node0 * K);
    for (int idx = tid; idx < 64 * K / 4; idx += 128) {
        float4 v = inv[idx];
        int row = idx / (K / 4), c4 = (idx % (K / 4)) * 4;
        uint4 h, l;
        split_tf32(v.x, h.x, l.x);
        split_tf32(v.y, h.y, l.y);
        split_tf32(v.z, h.z, l.z);
        split_tf32(v.w, h.w, l.w);
        *(uint4*)&As_hi[row * SA + c4] = h;
        *(uint4*)&As_lo[row * SA + c4] = l;
    }
    // Stage W: [n][k] global -> [k][n] smem
    for (int idx = tid; idx < 128 * K; idx += 128) {
        int n = idx / K, k = idx % K;
        Ws_hi[k * SW + n] = Whi[idx];
        Ws_lo[k * SW + n] = Wlo[idx];
    }
    __syncthreads();

    const int warp = tid >> 5, lane = tid & 31;
    const int g = lane >> 2, t = lane & 3;
    const int m0 = warp * 16;

    float c[16][4];
#pragma unroll
    for (int nt = 0; nt < 16; nt++)
#pragma unroll
        for (int j = 0; j < 4; j++) c[nt][j] = 0.f;

    for (int ks = 0; ks < K / 8; ks++) {
        const int ka = ks * 8 + t;
        uint32_t ah0 = As_hi[(m0 + g) * SA + ka];
        uint32_t ah1 = As_hi[(m0 + g + 8) * SA + ka];
        uint32_t ah2 = As_hi[(m0 + g) * SA + ka + 4];
        uint32_t ah3 = As_hi[(m0 + g + 8) * SA + ka + 4];
        uint32_t al0 = As_lo[(m0 + g) * SA + ka];
        uint32_t al1 = As_lo[(m0 + g + 8) * SA + ka];
        uint32_t al2 = As_lo[(m0 + g) * SA + ka + 4];
        uint32_t al3 = As_lo[(m0 + g + 8) * SA + ka + 4];
#pragma unroll
        for (int nt = 0; nt < 16; nt++) {
            int bi = ka * SW + nt * 8 + g;
            uint32_t bh0 = Ws_hi[bi], bh1 = Ws_hi[bi + 4 * SW];
            uint32_t bl0 = Ws_lo[bi], bl1 = Ws_lo[bi + 4 * SW];
            MMA_TF32(c[nt], ah0, ah1, ah2, ah3, bh0, bh1);
            MMA_TF32(c[nt], al0, al1, al2, al3, bh0, bh1);
            MMA_TF32(c[nt], ah0, ah1, ah2, ah3, bl0, bl1);
        }
    }

    // Epilogue: c[nt] rows (m0+g, m0+g+8), cols nt*8 + 2t (+1)
#pragma unroll
    for (int nt = 0; nt < 16; nt++) {
        float* base = (nt < 8) ? G_ZL : G_ZR;
        int col = ((nt < 8) ? nt * 8 : nt * 8 - 64) + 2 * t;
        size_t r0 = (size_t)(node0 + m0 + g);
        *(float2*)&base[r0 * D_EMB + col]       = make_float2(c[nt][0], c[nt][1]);
        *(float2*)&base[(r0 + 8) * D_EMB + col] = make_float2(c[nt][2], c[nt][3]);
    }
}

// ================== fused gather-aggregate + epilogue =========================
__global__ void gather_h_kernel(const float* __restrict__ b) {
    const int lane = threadIdx.x & 31;
    const int node = blockIdx.x * 8 + (threadIdx.x >> 5);
    if (node >= N_NODES) return;

    const int beg = g_off[node];
    const int deg = g_deg[node];
    const int end = beg + deg;

    const float2* zl2 = (const float2*)G_ZL;
    float2 s = make_float2(0.f, 0.f);

    int j = beg;
    for (; j + 4 <= end; j += 4) {
        int i0 = g_csr[j], i1 = g_csr[j + 1], i2 = g_csr[j + 2], i3 = g_csr[j + 3];
        float2 v0 = __ldg(&zl2[i0 * 32 + lane]);
        float2 v1 = __ldg(&zl2[i1 * 32 + lane]);
        float2 v2 = __ldg(&zl2[i2 * 32 + lane]);
        float2 v3 = __ldg(&zl2[i3 * 32 + lane]);
        s.x += (v0.x + v1.x) + (v2.x + v3.x);
        s.y += (v0.y + v1.y) + (v2.y + v3.y);
    }
    for (; j < end; j++) {
        float2 v = __ldg(&zl2[g_csr[j] * 32 + lane]);
        s.x += v.x; s.y += v.y;
    }

    const float inv = 1.0f / (float)max(deg, 1);
    const float2 zr = ((const float2*)G_ZR)[node * 32 + lane];
    float2 h;
    h.x = s.x * inv + __ldg(&b[lane * 2])     + zr.x;
    h.y = s.y * inv + __ldg(&b[lane * 2 + 1]) + zr.y;
    ((float2*)G_H)[node * 32 + lane] = h;
}

// ================== graph mean pool ==========================================
__global__ void pool_kernel() {
    __shared__ float red[256];
    const int g = blockIdx.x, tid = threadIdx.x;
    const int d = tid & 63, part = tid >> 6;
    const float* base = G_H + (size_t)g * NODES_PER_GRAPH * D_EMB;
    float s = 0.f;
    for (int n = part; n < NODES_PER_GRAPH; n += 4)
        s += base[n * D_EMB + d];
    red[tid] = s;
    __syncthreads();
    if (part == 0) {
        float t = red[d] + red[64 + d] + red[128 + d] + red[192 + d];
        g_pool[g * D_EMB + d] = t * (1.0f / NODES_PER_GRAPH);
    }
}

// ================== MLP head =================================================
__global__ void head_kernel(const float* __restrict__ fc1_W,
                            const float* __restrict__ fc1_b,
                            const float* __restrict__ fc2_W,
                            const float* __restrict__ fc2_b,
                            float* __restrict__ out) {
    __shared__ float gs[D_EMB];
    __shared__ float hs[D_HID];
    const int g = blockIdx.x, tid = threadIdx.x;
    if (tid < D_EMB) gs[tid] = g_pool[g * D_EMB + tid];
    __syncthreads();
    if (tid < D_HID) {
        float acc = fc1_b[tid];
        const float* w = fc1_W + (size_t)tid * D_EMB;
#pragma unroll
        for (int k = 0; k < D_EMB; k++) acc += gs[k] * w[k];
        hs[tid] = fmaxf(acc, 0.f);
    }
    __syncthreads();
    for (int a = tid; a < N_ACT; a += 256) {
        const float4* w = (const float4*)(fc2_W + (size_t)a * D_HID);
        float a0 = 0.f, a1 = 0.f, a2 = 0.f, a3 = 0.f;
#pragma unroll
        for (int k = 0; k < D_HID / 4; k++) {
            float4 wv = __ldg(&w[k]);
            a0 += wv.x * hs[4 * k + 0];
            a1 += wv.y * hs[4 * k + 1];
            a2 += wv.z * hs[4 * k + 2];
            a3 += wv.w * hs[4 * k + 3];
        }
        out[(size_t)g * N_ACT + a] = fc2_b[a] + (a0 + a1) + (a2 + a3);
    }
}

// ================== launch ===================================================
extern "C" void kernel_launch(void* const* d_in, const int* in_sizes, int n_in,
                              void* d_out, int out_size) {
    const float* x     = (const float*)d_in[0];
    const int*   ei    = (const int*)d_in[1];
    const float* W1l   = (const float*)d_in[2];
    const float* b1l   = (const float*)d_in[3];
    const float* W1r   = (const float*)d_in[4];
    const float* W2l   = (const float*)d_in[5];
    const float* b2l   = (const float*)d_in[6];
    const float* W2r   = (const float*)d_in[7];
    const float* fc1_W = (const float*)d_in[8];
    const float* fc1_b = (const float*)d_in[9];
    const float* fc2_W = (const float*)d_in[10];
    const float* fc2_b = (const float*)d_in[11];
    float* out = (float*)d_out;

    const int* src = ei;
    const int* dst = ei + N_EDGES;

    const int SMEM1 = (64 * (D_IN + 4) * 2 + D_IN * 136 * 2) * 4;   // 206848 B
    const int SMEM2 = (64 * (D_EMB + 4) * 2 + D_EMB * 136 * 2) * 4; // 104448 B
    cudaFuncSetAttribute(lin_tc_kernel<D_IN>,  cudaFuncAttributeMaxDynamicSharedMemorySize, SMEM1);
    cudaFuncSetAttribute(lin_tc_kernel<D_EMB>, cudaFuncAttributeMaxDynamicSharedMemorySize, SMEM2);

    // CSR prologue interleaved so lin_tc<128> is the 4th launch (profiler slot)
    deg_zero_kernel<<<N_NODES / 256, 256>>>();
    hist_kernel<<<2048, 256>>>(dst);
    wsplit_kernel<<<64, 256>>>(W1l, W1r, W2l, W2r);
    lin_tc_kernel<D_IN><<<N_NODES / 64, 128, SMEM1>>>(x);

    blocksum_kernel<<<SCAN_BLOCKS, 256>>>();
    scan_blk_kernel<<<1, SCAN_BLOCKS>>>();
    offsets_kernel<<<SCAN_BLOCKS, 256>>>();
    scatter_kernel<<<2048, 256>>>(src, dst);

    gather_h_kernel<<<N_NODES / 8, 256>>>(b1l);

    lin_tc_kernel<D_EMB><<<N_NODES / 64, 128, SMEM2>>>(nullptr);
    gather_h_kernel<<<N_NODES / 8, 256>>>(b2l);

    pool_kernel<<<N_GRAPHS, 256>>>();
    head_kernel<<<N_GRAPHS, 256>>>(fc1_W, fc1_b, fc2_W, fc2_b, out);
}

// round 5
// speedup vs baseline: 1.3865x; 1.3581x over previous
#include <cuda_runtime.h>
#include <cstdint>

#define N_NODES 131072
#define N_EDGES 2097152
#define N_GRAPHS 64
#define NODES_PER_GRAPH 2048
#define D_IN 128
#define D_EMB 64
#define D_HID 128
#define N_ACT 2048

#define SCAN_BLOCKS 512           // 512 * 256 = 131072

// ---------------- scratch (device globals) -----------------------------------
__device__ float4 g_zl4 [N_NODES * D_EMB / 4];   // in @ Wl.T (messages)
__device__ float4 g_zr4 [N_NODES * D_EMB / 4];   // in @ Wr.T (self term)
__device__ float4 g_h4  [N_NODES * D_EMB / 4];   // h1 then h2
__device__ float  g_pool[N_GRAPHS * D_EMB];

__device__ int g_deg [N_NODES];
__device__ int g_off [N_NODES];
__device__ int g_cur [N_NODES];
__device__ int g_csr [N_EDGES];
__device__ int g_blksum[SCAN_BLOCKS];
__device__ int g_blkoff[SCAN_BLOCKS];

// pre-split tf32 weights, layout [n][k], n<64 -> Wl row, n>=64 -> Wr row
__device__ uint32_t g_w1hi[128 * 128];
__device__ uint32_t g_w1lo[128 * 128];
__device__ uint32_t g_w2hi[128 * 64];
__device__ uint32_t g_w2lo[128 * 64];

#define G_ZL  ((float*)g_zl4)
#define G_ZR  ((float*)g_zr4)
#define G_H   ((float*)g_h4)

// ---------------- tf32 helpers ------------------------------------------------
__device__ __forceinline__ void split_tf32(float v, uint32_t& hi, uint32_t& lo) {
    asm("cvt.rna.tf32.f32 %0, %1;" : "=r"(hi) : "f"(v));
    float r = v - __uint_as_float(hi);
    asm("cvt.rna.tf32.f32 %0, %1;" : "=r"(lo) : "f"(r));
}

#define MMA_TF32(C, a0, a1, a2, a3, b0, b1)                                   \
    asm volatile(                                                             \
        "mma.sync.aligned.m16n8k8.row.col.f32.tf32.tf32.f32 "                 \
        "{%0,%1,%2,%3}, {%4,%5,%6,%7}, {%8,%9}, {%0,%1,%2,%3};"               \
        : "+f"((C)[0]), "+f"((C)[1]), "+f"((C)[2]), "+f"((C)[3])              \
        : "r"(a0), "r"(a1), "r"(a2), "r"(a3), "r"(b0), "r"(b1))

// ================== CSR build =================================================
__global__ void deg_zero_kernel() {
    int i = blockIdx.x * blockDim.x + threadIdx.x;
    if (i < N_NODES) g_deg[i] = 0;
}

__global__ void hist_kernel(const int* __restrict__ dst) {
    int stride = gridDim.x * blockDim.x;
    for (int e = blockIdx.x * blockDim.x + threadIdx.x; e < N_EDGES; e += stride)
        atomicAdd(&g_deg[dst[e]], 1);
}

__global__ void blocksum_kernel() {
    __shared__ int red[256];
    int i = blockIdx.x * 256 + threadIdx.x;
    red[threadIdx.x] = g_deg[i];
    __syncthreads();
    for (int s = 128; s > 0; s >>= 1) {
        if (threadIdx.x < s) red[threadIdx.x] += red[threadIdx.x + s];
        __syncthreads();
    }
    if (threadIdx.x == 0) g_blksum[blockIdx.x] = red[0];
}

__global__ void scan_blk_kernel() {
    __shared__ int sm[SCAN_BLOCKS];
    int t = threadIdx.x;
    sm[t] = g_blksum[t];
    __syncthreads();
    for (int d = 1; d < SCAN_BLOCKS; d <<= 1) {
        int v = (t >= d) ? sm[t - d] : 0;
        __syncthreads();
        sm[t] += v;
        __syncthreads();
    }
    g_blkoff[t] = sm[t] - g_blksum[t];
}

__global__ void offsets_kernel() {
    __shared__ int sm[256];
    int i = blockIdx.x * 256 + threadIdx.x;
    int t = threadIdx.x;
    int d = g_deg[i];
    sm[t] = d;
    __syncthreads();
    for (int s = 1; s < 256; s <<= 1) {
        int v = (t >= s) ? sm[t - s] : 0;
        __syncthreads();
        sm[t] += v;
        __syncthreads();
    }
    int off = g_blkoff[blockIdx.x] + sm[t] - d;
    g_off[i] = off;
    g_cur[i] = off;
}

__global__ void scatter_kernel(const int* __restrict__ src,
                               const int* __restrict__ dst) {
    int stride = gridDim.x * blockDim.x;
    for (int e = blockIdx.x * blockDim.x + threadIdx.x; e < N_EDGES; e += stride) {
        int d = dst[e];
        int pos = atomicAdd(&g_cur[d], 1);
        g_csr[pos] = src[e];
    }
}

// ================== weight pre-split (once) ===================================
__global__ void wsplit_kernel(const float* __restrict__ W1l,
                              const float* __restrict__ W1r,
                              const float* __restrict__ W2l,
                              const float* __restrict__ W2r) {
    int i = blockIdx.x * blockDim.x + threadIdx.x;
    if (i < 128 * 128) {
        int n = i >> 7, k = i & 127;
        float v = (n < 64) ? W1l[n * 128 + k] : W1r[(n - 64) * 128 + k];
        uint32_t hi, lo;
        split_tf32(v, hi, lo);
        g_w1hi[i] = hi; g_w1lo[i] = lo;
    }
    if (i < 128 * 64) {
        int n = i >> 6, k = i & 63;
        float v = (n < 64) ? W2l[n * 64 + k] : W2r[(n - 64) * 64 + k];
        uint32_t hi, lo;
        split_tf32(v, hi, lo);
        g_w2hi[i] = hi; g_w2lo[i] = lo;
    }
}

// ================== tensor-core dual projection (3xTF32) ======================
// Block: 128 nodes x 128 outputs (64 -> zl, 64 -> zr), 256 threads = 8 warps.
// Warp w computes rows [w*16, w*16+16) x all 128 outputs via m16n8k8 mma.
// A stays f32 in smem (split to tf32 hi/lo in registers); W is pre-split.
// K=128: smem 207KB -> 1 CTA/SM (8 warps). K=64: 104KB -> 2 CTA/SM (16 warps).
template <int K>
__global__ void __launch_bounds__(256) lin_tc_kernel(const float* __restrict__ in_param) {
    constexpr int SA = K + 4;        // A row stride: (K+4)%32==4 -> frag loads conflict-free
    constexpr int SW = 136;          // W row stride: 136%32==8  -> B loads conflict-free
    extern __shared__ uint32_t sm[];
    float*    As    = (float*)sm;                 // [128][SA] f32
    uint32_t* Ws_hi = sm + 128 * SA;              // [K][SW]
    uint32_t* Ws_lo = Ws_hi + K * SW;

    const float*    in  = (K == D_EMB) ? G_H    : in_param;  // layer 2 reads h1
    const uint32_t* Whi = (K == D_EMB) ? g_w2hi : g_w1hi;
    const uint32_t* Wlo = (K == D_EMB) ? g_w2lo : g_w1lo;

    const int tid = threadIdx.x;
    const int node0 = blockIdx.x * 128;

    // Stage A (plain f32, vectorized)
    const float4* inv = (const float4*)(in + (size_t)node0 * K);
    for (int idx = tid; idx < 128 * K / 4; idx += 256) {
        int row = idx / (K / 4), c4 = (idx % (K / 4)) * 4;
        *(float4*)&As[row * SA + c4] = inv[idx];
    }
    // Stage W: [n][k] global -> [k][n] smem (hi and lo)
    for (int idx = tid; idx < 128 * K; idx += 256) {
        int n = idx / K, k = idx % K;
        Ws_hi[k * SW + n] = Whi[idx];
        Ws_lo[k * SW + n] = Wlo[idx];
    }
    __syncthreads();

    const int warp = tid >> 5, lane = tid & 31;
    const int g = lane >> 2, t = lane & 3;
    const int m0 = warp * 16;

    float c[16][4];
#pragma unroll
    for (int nt = 0; nt < 16; nt++)
#pragma unroll
        for (int j = 0; j < 4; j++) c[nt][j] = 0.f;

#pragma unroll 2
    for (int ks = 0; ks < K / 8; ks++) {
        const int ka = ks * 8 + t;
        // load A fragment as f32, split to hi/lo in registers
        float a_f0 = As[(m0 + g) * SA + ka];
        float a_f1 = As[(m0 + g + 8) * SA + ka];
        float a_f2 = As[(m0 + g) * SA + ka + 4];
        float a_f3 = As[(m0 + g + 8) * SA + ka + 4];
        uint32_t ah0, al0, ah1, al1, ah2, al2, ah3, al3;
        split_tf32(a_f0, ah0, al0);
        split_tf32(a_f1, ah1, al1);
        split_tf32(a_f2, ah2, al2);
        split_tf32(a_f3, ah3, al3);
#pragma unroll
        for (int nt = 0; nt < 16; nt++) {
            int bi = ka * SW + nt * 8 + g;
            uint32_t bh0 = Ws_hi[bi], bh1 = Ws_hi[bi + 4 * SW];
            uint32_t bl0 = Ws_lo[bi], bl1 = Ws_lo[bi + 4 * SW];
            MMA_TF32(c[nt], ah0, ah1, ah2, ah3, bh0, bh1);
            MMA_TF32(c[nt], al0, al1, al2, al3, bh0, bh1);
            MMA_TF32(c[nt], ah0, ah1, ah2, ah3, bl0, bl1);
        }
    }

    // Epilogue: c[nt] rows (m0+g, m0+g+8), cols nt*8 + 2t (+1)
#pragma unroll
    for (int nt = 0; nt < 16; nt++) {
        float* base = (nt < 8) ? G_ZL : G_ZR;
        int col = ((nt < 8) ? nt * 8 : nt * 8 - 64) + 2 * t;
        size_t r0 = (size_t)(node0 + m0 + g);
        *(float2*)&base[r0 * D_EMB + col]       = make_float2(c[nt][0], c[nt][1]);
        *(float2*)&base[(r0 + 8) * D_EMB + col] = make_float2(c[nt][2], c[nt][3]);
    }
}

// ================== fused gather-aggregate + epilogue =========================
__global__ void gather_h_kernel(const float* __restrict__ b) {
    const int lane = threadIdx.x & 31;
    const int node = blockIdx.x * 8 + (threadIdx.x >> 5);
    if (node >= N_NODES) return;

    const int beg = g_off[node];
    const int deg = g_deg[node];
    const int end = beg + deg;

    const float2* zl2 = (const float2*)G_ZL;
    float2 s = make_float2(0.f, 0.f);

    int j = beg;
    for (; j + 4 <= end; j += 4) {
        int i0 = g_csr[j], i1 = g_csr[j + 1], i2 = g_csr[j + 2], i3 = g_csr[j + 3];
        float2 v0 = __ldg(&zl2[i0 * 32 + lane]);
        float2 v1 = __ldg(&zl2[i1 * 32 + lane]);
        float2 v2 = __ldg(&zl2[i2 * 32 + lane]);
        float2 v3 = __ldg(&zl2[i3 * 32 + lane]);
        s.x += (v0.x + v1.x) + (v2.x + v3.x);
        s.y += (v0.y + v1.y) + (v2.y + v3.y);
    }
    for (; j < end; j++) {
        float2 v = __ldg(&zl2[g_csr[j] * 32 + lane]);
        s.x += v.x; s.y += v.y;
    }

    const float inv = 1.0f / (float)max(deg, 1);
    const float2 zr = ((const float2*)G_ZR)[node * 32 + lane];
    float2 h;
    h.x = s.x * inv + __ldg(&b[lane * 2])     + zr.x;
    h.y = s.y * inv + __ldg(&b[lane * 2 + 1]) + zr.y;
    ((float2*)G_H)[node * 32 + lane] = h;
}

// ================== graph mean pool ==========================================
__global__ void pool_kernel() {
    __shared__ float red[256];
    const int g = blockIdx.x, tid = threadIdx.x;
    const int d = tid & 63, part = tid >> 6;
    const float* base = G_H + (size_t)g * NODES_PER_GRAPH * D_EMB;
    float s = 0.f;
    for (int n = part; n < NODES_PER_GRAPH; n += 4)
        s += base[n * D_EMB + d];
    red[tid] = s;
    __syncthreads();
    if (part == 0) {
        float t = red[d] + red[64 + d] + red[128 + d] + red[192 + d];
        g_pool[g * D_EMB + d] = t * (1.0f / NODES_PER_GRAPH);
    }
}

// ================== MLP head =================================================
__global__ void head_kernel(const float* __restrict__ fc1_W,
                            const float* __restrict__ fc1_b,
                            const float* __restrict__ fc2_W,
                            const float* __restrict__ fc2_b,
                            float* __restrict__ out) {
    __shared__ float gs[D_EMB];
    __shared__ float hs[D_HID];
    const int g = blockIdx.x, tid = threadIdx.x;
    if (tid < D_EMB) gs[tid] = g_pool[g * D_EMB + tid];
    __syncthreads();
    if (tid < D_HID) {
        float acc = fc1_b[tid];
        const float* w = fc1_W + (size_t)tid * D_EMB;
#pragma unroll
        for (int k = 0; k < D_EMB; k++) acc += gs[k] * w[k];
        hs[tid] = fmaxf(acc, 0.f);
    }
    __syncthreads();
    for (int a = tid; a < N_ACT; a += 256) {
        const float4* w = (const float4*)(fc2_W + (size_t)a * D_HID);
        float a0 = 0.f, a1 = 0.f, a2 = 0.f, a3 = 0.f;
#pragma unroll
        for (int k = 0; k < D_HID / 4; k++) {
            float4 wv = __ldg(&w[k]);
            a0 += wv.x * hs[4 * k + 0];
            a1 += wv.y * hs[4 * k + 1];
            a2 += wv.z * hs[4 * k + 2];
            a3 += wv.w * hs[4 * k + 3];
        }
        out[(size_t)g * N_ACT + a] = fc2_b[a] + (a0 + a1) + (a2 + a3);
    }
}

// ================== launch ===================================================
extern "C" void kernel_launch(void* const* d_in, const int* in_sizes, int n_in,
                              void* d_out, int out_size) {
    const float* x     = (const float*)d_in[0];
    const int*   ei    = (const int*)d_in[1];
    const float* W1l   = (const float*)d_in[2];
    const float* b1l   = (const float*)d_in[3];
    const float* W1r   = (const float*)d_in[4];
    const float* W2l   = (const float*)d_in[5];
    const float* b2l   = (const float*)d_in[6];
    const float* W2r   = (const float*)d_in[7];
    const float* fc1_W = (const float*)d_in[8];
    const float* fc1_b = (const float*)d_in[9];
    const float* fc2_W = (const float*)d_in[10];
    const float* fc2_b = (const float*)d_in[11];
    float* out = (float*)d_out;

    const int* src = ei;
    const int* dst = ei + N_EDGES;

    const int SMEM1 = (128 * (D_IN + 4) + D_IN * 136 * 2) * 4;   // 206848 B
    const int SMEM2 = (128 * (D_EMB + 4) + D_EMB * 136 * 2) * 4; // 104448 B
    cudaFuncSetAttribute(lin_tc_kernel<D_IN>,  cudaFuncAttributeMaxDynamicSharedMemorySize, SMEM1);
    cudaFuncSetAttribute(lin_tc_kernel<D_EMB>, cudaFuncAttributeMaxDynamicSharedMemorySize, SMEM2);

    // lin_tc<128> kept as 4th launch (profiler capture slot)
    deg_zero_kernel<<<N_NODES / 256, 256>>>();
    hist_kernel<<<2048, 256>>>(dst);
    wsplit_kernel<<<64, 256>>>(W1l, W1r, W2l, W2r);
    lin_tc_kernel<D_IN><<<N_NODES / 128, 256, SMEM1>>>(x);

    blocksum_kernel<<<SCAN_BLOCKS, 256>>>();
    scan_blk_kernel<<<1, SCAN_BLOCKS>>>();
    offsets_kernel<<<SCAN_BLOCKS, 256>>>();
    scatter_kernel<<<2048, 256>>>(src, dst);

    gather_h_kernel<<<N_NODES / 8, 256>>>(b1l);

    lin_tc_kernel<D_EMB><<<N_NODES / 128, 256, SMEM2>>>(nullptr);
    gather_h_kernel<<<N_NODES / 8, 256>>>(b2l);

    pool_kernel<<<N_GRAPHS, 256>>>();
    head_kernel<<<N_GRAPHS, 256>>>(fc1_W, fc1_b, fc2_W, fc2_b, out);
}

// round 6
// speedup vs baseline: 1.5615x; 1.1262x over previous
#include <cuda_runtime.h>
#include <cuda_bf16.h>
#include <cstdint>

#define N_NODES 131072
#define N_EDGES 2097152
#define N_GRAPHS 64
#define NODES_PER_GRAPH 2048
#define D_IN 128
#define D_EMB 64
#define D_HID 128
#define N_ACT 2048

#define SCAN_BLOCKS 512           // 512 * 256 = 131072

// ---------------- scratch (device globals) -----------------------------------
__device__ float4 g_zl4 [N_NODES * D_EMB / 4];   // in @ Wl.T (messages)
__device__ float4 g_zr4 [N_NODES * D_EMB / 4];   // in @ Wr.T (self term)
__device__ float4 g_h4  [N_NODES * D_EMB / 4];   // h1 then h2
__device__ float  g_pool[N_GRAPHS * D_EMB];

__device__ int g_deg [N_NODES];
__device__ int g_off [N_NODES];
__device__ int g_cur [N_NODES];
__device__ int g_csr [N_EDGES];
__device__ int g_blksum[SCAN_BLOCKS];
__device__ int g_blkoff[SCAN_BLOCKS];

// pre-split bf16 weights, packed pairs (uint32 = 2 bf16), layout [n][k]
// n<64 -> Wl row, n>=64 -> Wr row
__device__ uint32_t g_w1h_u[128 * 128 / 2];
__device__ uint32_t g_w1l_u[128 * 128 / 2];
__device__ uint32_t g_w2h_u[128 * 64 / 2];
__device__ uint32_t g_w2l_u[128 * 64 / 2];

#define G_ZL  ((float*)g_zl4)
#define G_ZR  ((float*)g_zr4)
#define G_H   ((float*)g_h4)

// ---------------- bf16 helpers -------------------------------------------------
__device__ __forceinline__ uint32_t pack_bf16(__nv_bfloat16 a, __nv_bfloat16 b) {
    __nv_bfloat162 p = __halves2bfloat162(a, b);   // a in low half (element k)
    return *reinterpret_cast<uint32_t*>(&p);
}

// split f32 pair -> packed hi pair + packed lo pair
__device__ __forceinline__ void split_pair(float v0, float v1,
                                           uint32_t& hi, uint32_t& lo) {
    __nv_bfloat16 h0 = __float2bfloat16_rn(v0);
    __nv_bfloat16 h1 = __float2bfloat16_rn(v1);
    __nv_bfloat16 l0 = __float2bfloat16_rn(v0 - __bfloat162float(h0));
    __nv_bfloat16 l1 = __float2bfloat16_rn(v1 - __bfloat162float(h1));
    hi = pack_bf16(h0, h1);
    lo = pack_bf16(l0, l1);
}

#define MMA_BF16(C, a0, a1, a2, a3, b0, b1)                                   \
    asm volatile(                                                             \
        "mma.sync.aligned.m16n8k16.row.col.f32.bf16.bf16.f32 "                \
        "{%0,%1,%2,%3}, {%4,%5,%6,%7}, {%8,%9}, {%0,%1,%2,%3};"               \
        : "+f"((C)[0]), "+f"((C)[1]), "+f"((C)[2]), "+f"((C)[3])              \
        : "r"(a0), "r"(a1), "r"(a2), "r"(a3), "r"(b0), "r"(b1))

// ================== CSR build =================================================
__global__ void deg_zero_kernel() {
    int i = blockIdx.x * blockDim.x + threadIdx.x;
    if (i < N_NODES) g_deg[i] = 0;
}

__global__ void hist_kernel(const int* __restrict__ dst) {
    int stride = gridDim.x * blockDim.x;
    for (int e = blockIdx.x * blockDim.x + threadIdx.x; e < N_EDGES; e += stride)
        atomicAdd(&g_deg[dst[e]], 1);
}

__global__ void blocksum_kernel() {
    __shared__ int red[256];
    int i = blockIdx.x * 256 + threadIdx.x;
    red[threadIdx.x] = g_deg[i];
    __syncthreads();
    for (int s = 128; s > 0; s >>= 1) {
        if (threadIdx.x < s) red[threadIdx.x] += red[threadIdx.x + s];
        __syncthreads();
    }
    if (threadIdx.x == 0) g_blksum[blockIdx.x] = red[0];
}

__global__ void scan_blk_kernel() {
    __shared__ int sm[SCAN_BLOCKS];
    int t = threadIdx.x;
    sm[t] = g_blksum[t];
    __syncthreads();
    for (int d = 1; d < SCAN_BLOCKS; d <<= 1) {
        int v = (t >= d) ? sm[t - d] : 0;
        __syncthreads();
        sm[t] += v;
        __syncthreads();
    }
    g_blkoff[t] = sm[t] - g_blksum[t];
}

__global__ void offsets_kernel() {
    __shared__ int sm[256];
    int i = blockIdx.x * 256 + threadIdx.x;
    int t = threadIdx.x;
    int d = g_deg[i];
    sm[t] = d;
    __syncthreads();
    for (int s = 1; s < 256; s <<= 1) {
        int v = (t >= s) ? sm[t - s] : 0;
        __syncthreads();
        sm[t] += v;
        __syncthreads();
    }
    int off = g_blkoff[blockIdx.x] + sm[t] - d;
    g_off[i] = off;
    g_cur[i] = off;
}

__global__ void scatter_kernel(const int* __restrict__ src,
                               const int* __restrict__ dst) {
    int stride = gridDim.x * blockDim.x;
    for (int e = blockIdx.x * blockDim.x + threadIdx.x; e < N_EDGES; e += stride) {
        int d = dst[e];
        int pos = atomicAdd(&g_cur[d], 1);
        g_csr[pos] = src[e];
    }
}

// ================== weight pre-split to bf16 pairs (once) =====================
__global__ void wsplit_kernel(const float* __restrict__ W1l,
                              const float* __restrict__ W1r,
                              const float* __restrict__ W2l,
                              const float* __restrict__ W2r) {
    int i = blockIdx.x * blockDim.x + threadIdx.x;   // pair index
    if (i < 128 * 64) {          // W1: 128 n-rows x 128 k = 8192 pairs
        int n = i >> 6, k2 = (i & 63) * 2;
        const float* W = (n < 64) ? (W1l + n * 128) : (W1r + (n - 64) * 128);
        uint32_t hi, lo;
        split_pair(W[k2], W[k2 + 1], hi, lo);
        g_w1h_u[i] = hi; g_w1l_u[i] = lo;
    }
    if (i < 128 * 32) {          // W2: 128 n-rows x 64 k = 4096 pairs
        int n = i >> 5, k2 = (i & 31) * 2;
        const float* W = (n < 64) ? (W2l + n * 64) : (W2r + (n - 64) * 64);
        uint32_t hi, lo;
        split_pair(W[k2], W[k2 + 1], hi, lo);
        g_w2h_u[i] = hi; g_w2l_u[i] = lo;
    }
}

// ================== tensor-core dual projection (3xBF16, m16n8k16) ============
// Block: 128 nodes x 128 outputs (64 -> zl, 64 -> zr), 256 threads = 8 warps.
// Warp tile: 32 rows x 64 cols (2 m-tiles x 8 n-tiles).
// All operands staged as packed bf16 pairs (uint32). Row stride SU u32 words,
// SU % 32 == 4 -> fragment loads conflict-free (lane word = 4g + t, distinct).
template <int K>
__global__ void __launch_bounds__(256) lin_tc_kernel(const float* __restrict__ in_param) {
    constexpr int SU = K / 2 + 4;   // u32 words per row (68 for K=128, 36 for K=64)
    extern __shared__ uint32_t sm[];
    uint32_t* Ah = sm;              // [128][SU]
    uint32_t* Al = Ah + 128 * SU;
    uint32_t* Wh = Al + 128 * SU;   // [128 n][SU]
    uint32_t* Wl = Wh + 128 * SU;

    const float*    in  = (K == D_EMB) ? G_H     : in_param;  // layer 2 reads h1
    const uint32_t* Whu = (K == D_EMB) ? g_w2h_u : g_w1h_u;
    const uint32_t* Wlu = (K == D_EMB) ? g_w2l_u : g_w1l_u;

    const int tid = threadIdx.x;
    const int node0 = blockIdx.x * 128;

    // Stage A: f32 -> split bf16 pairs
    const float4* inv = (const float4*)(in + (size_t)node0 * K);
    for (int idx = tid; idx < 128 * K / 4; idx += 256) {
        float4 v = inv[idx];
        int row = idx / (K / 4), w0 = (idx % (K / 4)) * 2;   // u32 word offset
        uint32_t h01, l01, h23, l23;
        split_pair(v.x, v.y, h01, l01);
        split_pair(v.z, v.w, h23, l23);
        Ah[row * SU + w0] = h01;  Ah[row * SU + w0 + 1] = h23;
        Al[row * SU + w0] = l01;  Al[row * SU + w0 + 1] = l23;
    }
    // Stage W (already pre-split; just re-stride)
    for (int idx = tid; idx < 128 * K / 2; idx += 256) {
        int n = idx / (K / 2), kp = idx % (K / 2);
        Wh[n * SU + kp] = Whu[idx];
        Wl[n * SU + kp] = Wlu[idx];
    }
    __syncthreads();

    const int warp = tid >> 5, lane = tid & 31;
    const int g = lane >> 2, t = lane & 3;
    const int m_base = (warp >> 1) * 32;      // 0,32,64,96
    const int cb     = (warp & 1) * 64;       // 0 -> zl, 64 -> zr

    float c[2][8][4];
#pragma unroll
    for (int mt = 0; mt < 2; mt++)
#pragma unroll
        for (int nt = 0; nt < 8; nt++)
#pragma unroll
            for (int j = 0; j < 4; j++) c[mt][nt][j] = 0.f;

#pragma unroll
    for (int ks = 0; ks < K / 16; ks++) {
        const int kk = ks * 8 + t;            // u32 word offset within row
        uint32_t ah[2][4], al[2][4];
#pragma unroll
        for (int mt = 0; mt < 2; mt++) {
            int r0 = m_base + mt * 16 + g;
            ah[mt][0] = Ah[r0 * SU + kk];
            ah[mt][1] = Ah[(r0 + 8) * SU + kk];
            ah[mt][2] = Ah[r0 * SU + kk + 4];
            ah[mt][3] = Ah[(r0 + 8) * SU + kk + 4];
            al[mt][0] = Al[r0 * SU + kk];
            al[mt][1] = Al[(r0 + 8) * SU + kk];
            al[mt][2] = Al[r0 * SU + kk + 4];
            al[mt][3] = Al[(r0 + 8) * SU + kk + 4];
        }
#pragma unroll
        for (int nt = 0; nt < 8; nt++) {
            int col = cb + nt * 8 + g;
            uint32_t bh0 = Wh[col * SU + kk], bh1 = Wh[col * SU + kk + 4];
            uint32_t bl0 = Wl[col * SU + kk], bl1 = Wl[col * SU + kk + 4];
#pragma unroll
            for (int mt = 0; mt < 2; mt++) {
                MMA_BF16(c[mt][nt], ah[mt][0], ah[mt][1], ah[mt][2], ah[mt][3], bh0, bh1);
                MMA_BF16(c[mt][nt], al[mt][0], al[mt][1], al[mt][2], al[mt][3], bh0, bh1);
                MMA_BF16(c[mt][nt], ah[mt][0], ah[mt][1], ah[mt][2], ah[mt][3], bl0, bl1);
            }
        }
    }

    // Epilogue: rows m_base+mt*16+g (+8), cols nt*8 + 2t (+1) in zl/zr per cb
    float* base = (cb == 0) ? G_ZL : G_ZR;
#pragma unroll
    for (int mt = 0; mt < 2; mt++) {
#pragma unroll
        for (int nt = 0; nt < 8; nt++) {
            int colg = nt * 8 + 2 * t;
            size_t r0 = (size_t)(node0 + m_base + mt * 16 + g);
            *(float2*)&base[r0 * D_EMB + colg]       = make_float2(c[mt][nt][0], c[mt][nt][1]);
            *(float2*)&base[(r0 + 8) * D_EMB + colg] = make_float2(c[mt][nt][2], c[mt][nt][3]);
        }
    }
}

// ================== fused gather-aggregate + epilogue =========================
__global__ void gather_h_kernel(const float* __restrict__ b) {
    const int lane = threadIdx.x & 31;
    const int node = blockIdx.x * 8 + (threadIdx.x >> 5);
    if (node >= N_NODES) return;

    const int beg = g_off[node];
    const int deg = g_deg[node];
    const int end = beg + deg;

    const float2* zl2 = (const float2*)G_ZL;
    float2 s = make_float2(0.f, 0.f);

    int j = beg;
    for (; j + 4 <= end; j += 4) {
        int i0 = g_csr[j], i1 = g_csr[j + 1], i2 = g_csr[j + 2], i3 = g_csr[j + 3];
        float2 v0 = __ldg(&zl2[i0 * 32 + lane]);
        float2 v1 = __ldg(&zl2[i1 * 32 + lane]);
        float2 v2 = __ldg(&zl2[i2 * 32 + lane]);
        float2 v3 = __ldg(&zl2[i3 * 32 + lane]);
        s.x += (v0.x + v1.x) + (v2.x + v3.x);
        s.y += (v0.y + v1.y) + (v2.y + v3.y);
    }
    for (; j < end; j++) {
        float2 v = __ldg(&zl2[g_csr[j] * 32 + lane]);
        s.x += v.x; s.y += v.y;
    }

    const float inv = 1.0f / (float)max(deg, 1);
    const float2 zr = ((const float2*)G_ZR)[node * 32 + lane];
    float2 h;
    h.x = s.x * inv + __ldg(&b[lane * 2])     + zr.x;
    h.y = s.y * inv + __ldg(&b[lane * 2 + 1]) + zr.y;
    ((float2*)G_H)[node * 32 + lane] = h;
}

// ================== graph mean pool ==========================================
__global__ void pool_kernel() {
    __shared__ float red[256];
    const int g = blockIdx.x, tid = threadIdx.x;
    const int d = tid & 63, part = tid >> 6;
    const float* base = G_H + (size_t)g * NODES_PER_GRAPH * D_EMB;
    float s = 0.f;
    for (int n = part; n < NODES_PER_GRAPH; n += 4)
        s += base[n * D_EMB + d];
    red[tid] = s;
    __syncthreads();
    if (part == 0) {
        float t = red[d] + red[64 + d] + red[128 + d] + red[192 + d];
        g_pool[g * D_EMB + d] = t * (1.0f / NODES_PER_GRAPH);
    }
}

// ================== MLP head =================================================
__global__ void head_kernel(const float* __restrict__ fc1_W,
                            const float* __restrict__ fc1_b,
                            const float* __restrict__ fc2_W,
                            const float* __restrict__ fc2_b,
                            float* __restrict__ out) {
    __shared__ float gs[D_EMB];
    __shared__ float hs[D_HID];
    const int g = blockIdx.x, tid = threadIdx.x;
    if (tid < D_EMB) gs[tid] = g_pool[g * D_EMB + tid];
    __syncthreads();
    if (tid < D_HID) {
        float acc = fc1_b[tid];
        const float* w = fc1_W + (size_t)tid * D_EMB;
#pragma unroll
        for (int k = 0; k < D_EMB; k++) acc += gs[k] * w[k];
        hs[tid] = fmaxf(acc, 0.f);
    }
    __syncthreads();
    for (int a = tid; a < N_ACT; a += 256) {
        const float4* w = (const float4*)(fc2_W + (size_t)a * D_HID);
        float a0 = 0.f, a1 = 0.f, a2 = 0.f, a3 = 0.f;
#pragma unroll
        for (int k = 0; k < D_HID / 4; k++) {
            float4 wv = __ldg(&w[k]);
            a0 += wv.x * hs[4 * k + 0];
            a1 += wv.y * hs[4 * k + 1];
            a2 += wv.z * hs[4 * k + 2];
            a3 += wv.w * hs[4 * k + 3];
        }
        out[(size_t)g * N_ACT + a] = fc2_b[a] + (a0 + a1) + (a2 + a3);
    }
}

// ================== launch ===================================================
extern "C" void kernel_launch(void* const* d_in, const int* in_sizes, int n_in,
                              void* d_out, int out_size) {
    const float* x     = (const float*)d_in[0];
    const int*   ei    = (const int*)d_in[1];
    const float* W1l   = (const float*)d_in[2];
    const float* b1l   = (const float*)d_in[3];
    const float* W1r   = (const float*)d_in[4];
    const float* W2l   = (const float*)d_in[5];
    const float* b2l   = (const float*)d_in[6];
    const float* W2r   = (const float*)d_in[7];
    const float* fc1_W = (const float*)d_in[8];
    const float* fc1_b = (const float*)d_in[9];
    const float* fc2_W = (const float*)d_in[10];
    const float* fc2_b = (const float*)d_in[11];
    float* out = (float*)d_out;

    const int* src = ei;
    const int* dst = ei + N_EDGES;

    const int SMEM1 = 4 * 128 * (D_IN / 2 + 4) * 4;   // 139264 B
    const int SMEM2 = 4 * 128 * (D_EMB / 2 + 4) * 4;  //  73728 B
    cudaFuncSetAttribute(lin_tc_kernel<D_IN>,  cudaFuncAttributeMaxDynamicSharedMemorySize, SMEM1);
    cudaFuncSetAttribute(lin_tc_kernel<D_EMB>, cudaFuncAttributeMaxDynamicSharedMemorySize, SMEM2);

    // lin_tc<128> kept as 4th launch (profiler capture slot)
    deg_zero_kernel<<<N_NODES / 256, 256>>>();
    hist_kernel<<<2048, 256>>>(dst);
    wsplit_kernel<<<32, 256>>>(W1l, W1r, W2l, W2r);
    lin_tc_kernel<D_IN><<<N_NODES / 128, 256, SMEM1>>>(x);

    blocksum_kernel<<<SCAN_BLOCKS, 256>>>();
    scan_blk_kernel<<<1, SCAN_BLOCKS>>>();
    offsets_kernel<<<SCAN_BLOCKS, 256>>>();
    scatter_kernel<<<2048, 256>>>(src, dst);

    gather_h_kernel<<<N_NODES / 8, 256>>>(b1l);

    lin_tc_kernel<D_EMB><<<N_NODES / 128, 256, SMEM2>>>(nullptr);
    gather_h_kernel<<<N_NODES / 8, 256>>>(b2l);

    pool_kernel<<<N_GRAPHS, 256>>>();
    head_kernel<<<N_GRAPHS, 256>>>(fc1_W, fc1_b, fc2_W, fc2_b, out);
}

// round 7
// speedup vs baseline: 1.6786x; 1.0750x over previous
#include <cuda_runtime.h>
#include <cuda_bf16.h>
#include <cstdint>

#define N_NODES 131072
#define N_EDGES 2097152
#define N_GRAPHS 64
#define NODES_PER_GRAPH 2048
#define D_IN 128
#define D_EMB 64
#define D_HID 128
#define N_ACT 2048

#define SCAN_BLOCKS 512           // 512 * 256 = 131072

// ---------------- scratch (device globals) -----------------------------------
__device__ float4 g_zl4 [N_NODES * D_EMB / 4];   // in @ Wl.T (messages)
__device__ float4 g_zr4 [N_NODES * D_EMB / 4];   // in @ Wr.T (self term)
__device__ float4 g_h4  [N_NODES * D_EMB / 4];   // h1 then h2
__device__ float  g_pool[N_GRAPHS * D_EMB];

__device__ int g_deg [N_NODES];
__device__ int g_off [N_NODES];
__device__ int g_cur [N_NODES];
__device__ int g_csr [N_EDGES];
__device__ int g_blksum[SCAN_BLOCKS];
__device__ int g_blkoff[SCAN_BLOCKS];

// fragment-packed bf16 weights: index ((ks*4 + t)*128 + col)
// uint4 = { hi pair @ ks*8+t, hi pair @ ks*8+t+4, lo pair @ ks*8+t, lo pair @ ks*8+t+4 }
// col < 64 -> Wl output col, col >= 64 -> Wr output col-64
__device__ uint4 g_w1f[(128 / 16) * 4 * 128];   // 4096 entries, 64 KB
__device__ uint4 g_w2f[(64 / 16) * 4 * 128];    // 2048 entries, 32 KB

#define G_ZL  ((float*)g_zl4)
#define G_ZR  ((float*)g_zr4)
#define G_H   ((float*)g_h4)

// ---------------- bf16 helpers -------------------------------------------------
__device__ __forceinline__ uint32_t pack_bf16(__nv_bfloat16 a, __nv_bfloat16 b) {
    __nv_bfloat162 p = __halves2bfloat162(a, b);   // a in low half (element k)
    return *reinterpret_cast<uint32_t*>(&p);
}

// split f32 pair -> packed hi pair + packed lo pair
__device__ __forceinline__ void split_pair(float v0, float v1,
                                           uint32_t& hi, uint32_t& lo) {
    __nv_bfloat16 h0 = __float2bfloat16_rn(v0);
    __nv_bfloat16 h1 = __float2bfloat16_rn(v1);
    __nv_bfloat16 l0 = __float2bfloat16_rn(v0 - __bfloat162float(h0));
    __nv_bfloat16 l1 = __float2bfloat16_rn(v1 - __bfloat162float(h1));
    hi = pack_bf16(h0, h1);
    lo = pack_bf16(l0, l1);
}

#define MMA_BF16(C, a0, a1, a2, a3, b0, b1)                                   \
    asm volatile(                                                             \
        "mma.sync.aligned.m16n8k16.row.col.f32.bf16.bf16.f32 "                \
        "{%0,%1,%2,%3}, {%4,%5,%6,%7}, {%8,%9}, {%0,%1,%2,%3};"               \
        : "+f"((C)[0]), "+f"((C)[1]), "+f"((C)[2]), "+f"((C)[3])              \
        : "r"(a0), "r"(a1), "r"(a2), "r"(a3), "r"(b0), "r"(b1))

// ================== CSR build =================================================
__global__ void deg_zero_kernel() {
    int i = blockIdx.x * blockDim.x + threadIdx.x;
    if (i < N_NODES) g_deg[i] = 0;
}

__global__ void hist_kernel(const int* __restrict__ dst) {
    int stride = gridDim.x * blockDim.x;
    for (int e = blockIdx.x * blockDim.x + threadIdx.x; e < N_EDGES; e += stride)
        atomicAdd(&g_deg[dst[e]], 1);
}

__global__ void blocksum_kernel() {
    __shared__ int red[256];
    int i = blockIdx.x * 256 + threadIdx.x;
    red[threadIdx.x] = g_deg[i];
    __syncthreads();
    for (int s = 128; s > 0; s >>= 1) {
        if (threadIdx.x < s) red[threadIdx.x] += red[threadIdx.x + s];
        __syncthreads();
    }
    if (threadIdx.x == 0) g_blksum[blockIdx.x] = red[0];
}

__global__ void scan_blk_kernel() {
    __shared__ int sm[SCAN_BLOCKS];
    int t = threadIdx.x;
    sm[t] = g_blksum[t];
    __syncthreads();
    for (int d = 1; d < SCAN_BLOCKS; d <<= 1) {
        int v = (t >= d) ? sm[t - d] : 0;
        __syncthreads();
        sm[t] += v;
        __syncthreads();
    }
    g_blkoff[t] = sm[t] - g_blksum[t];
}

__global__ void offsets_kernel() {
    __shared__ int sm[256];
    int i = blockIdx.x * 256 + threadIdx.x;
    int t = threadIdx.x;
    int d = g_deg[i];
    sm[t] = d;
    __syncthreads();
    for (int s = 1; s < 256; s <<= 1) {
        int v = (t >= s) ? sm[t - s] : 0;
        __syncthreads();
        sm[t] += v;
        __syncthreads();
    }
    int off = g_blkoff[blockIdx.x] + sm[t] - d;
    g_off[i] = off;
    g_cur[i] = off;
}

__global__ void scatter_kernel(const int* __restrict__ src,
                               const int* __restrict__ dst) {
    int stride = gridDim.x * blockDim.x;
    for (int e = blockIdx.x * blockDim.x + threadIdx.x; e < N_EDGES; e += stride) {
        int d = dst[e];
        int pos = atomicAdd(&g_cur[d], 1);
        g_csr[pos] = src[e];
    }
}

// ================== weight pre-split to fragment-packed uint4 (once) ==========
// Entry i = (ks*4 + t)*128 + col.
template <int K>
__device__ __forceinline__ uint4 make_wfrag(const float* __restrict__ Wrow,
                                            int ks, int t) {
    int p0 = ks * 8 + t;          // pair index for b0
    int p1 = ks * 8 + t + 4;      // pair index for b1
    uint4 f;
    uint32_t h0, l0, h1, l1;
    split_pair(Wrow[2 * p0], Wrow[2 * p0 + 1], h0, l0);
    split_pair(Wrow[2 * p1], Wrow[2 * p1 + 1], h1, l1);
    f.x = h0; f.y = h1; f.z = l0; f.w = l1;
    return f;
}

__global__ void wsplit_kernel(const float* __restrict__ W1l,
                              const float* __restrict__ W1r,
                              const float* __restrict__ W2l,
                              const float* __restrict__ W2r) {
    int i = blockIdx.x * blockDim.x + threadIdx.x;
    if (i < 8 * 4 * 128) {        // layer 1: ks<8
        int col = i & 127, tt = (i >> 7) & 3, ks = i >> 9;
        const float* Wrow = (col < 64) ? (W1l + col * 128) : (W1r + (col - 64) * 128);
        g_w1f[i] = make_wfrag<128>(Wrow, ks, tt);
    }
    if (i < 4 * 4 * 128) {        // layer 2: ks<4
        int col = i & 127, tt = (i >> 7) & 3, ks = i >> 9;
        const float* Wrow = (col < 64) ? (W2l + col * 64) : (W2r + (col - 64) * 64);
        g_w2f[i] = make_wfrag<64>(Wrow, ks, tt);
    }
}

// ================== tensor-core dual projection (3xBF16, m16n8k16) ============
// Block: 128 nodes x 128 outputs (64 -> zl, 64 -> zr), 256 threads = 8 warps.
// Warp tile: 32 rows x 64 cols (2 m-tiles x 8 n-tiles).
// A staged in smem as packed bf16 pairs; W read directly from L1-resident
// fragment-packed global table (one LDG.128 per n-tile per k-step).
// smem: K=128 -> 69.6KB, K=64 -> 36.9KB; launch_bounds forces 2 CTA/SM.
template <int K>
__global__ void __launch_bounds__(256, 2) lin_tc_kernel(const float* __restrict__ in_param) {
    constexpr int SU = K / 2 + 4;   // u32 words per row; SU%32==4 -> conflict-free frags
    extern __shared__ uint32_t sm[];
    uint32_t* Ah = sm;              // [128][SU]
    uint32_t* Al = Ah + 128 * SU;

    const float* in  = (K == D_EMB) ? G_H   : in_param;   // layer 2 reads h1
    const uint4* Wf  = (K == D_EMB) ? g_w2f : g_w1f;

    const int tid = threadIdx.x;
    const int node0 = blockIdx.x * 128;

    // Stage A: f32 -> split bf16 pairs
    const float4* inv = (const float4*)(in + (size_t)node0 * K);
    for (int idx = tid; idx < 128 * K / 4; idx += 256) {
        float4 v = inv[idx];
        int row = idx / (K / 4), w0 = (idx % (K / 4)) * 2;   // u32 word offset
        uint32_t h01, l01, h23, l23;
        split_pair(v.x, v.y, h01, l01);
        split_pair(v.z, v.w, h23, l23);
        Ah[row * SU + w0] = h01;  Ah[row * SU + w0 + 1] = h23;
        Al[row * SU + w0] = l01;  Al[row * SU + w0 + 1] = l23;
    }
    __syncthreads();

    const int warp = tid >> 5, lane = tid & 31;
    const int g = lane >> 2, t = lane & 3;
    const int m_base = (warp >> 1) * 32;      // 0,32,64,96
    const int cb     = (warp & 1) * 64;       // 0 -> zl, 64 -> zr

    float c[2][8][4];
#pragma unroll
    for (int mt = 0; mt < 2; mt++)
#pragma unroll
        for (int nt = 0; nt < 8; nt++)
#pragma unroll
            for (int j = 0; j < 4; j++) c[mt][nt][j] = 0.f;

#pragma unroll
    for (int ks = 0; ks < K / 16; ks++) {
        const int kk = ks * 8 + t;            // u32 word offset within row
        uint32_t ah[2][4], al[2][4];
#pragma unroll
        for (int mt = 0; mt < 2; mt++) {
            int r0 = m_base + mt * 16 + g;
            ah[mt][0] = Ah[r0 * SU + kk];
            ah[mt][1] = Ah[(r0 + 8) * SU + kk];
            ah[mt][2] = Ah[r0 * SU + kk + 4];
            ah[mt][3] = Ah[(r0 + 8) * SU + kk + 4];
            al[mt][0] = Al[r0 * SU + kk];
            al[mt][1] = Al[(r0 + 8) * SU + kk];
            al[mt][2] = Al[r0 * SU + kk + 4];
            al[mt][3] = Al[(r0 + 8) * SU + kk + 4];
        }
        const uint4* wrow = Wf + (size_t)(ks * 4 + t) * 128 + cb + g;
#pragma unroll
        for (int nt = 0; nt < 8; nt++) {
            uint4 f = __ldg(wrow + nt * 8);   // {bh0, bh1, bl0, bl1}
#pragma unroll
            for (int mt = 0; mt < 2; mt++) {
                MMA_BF16(c[mt][nt], ah[mt][0], ah[mt][1], ah[mt][2], ah[mt][3], f.x, f.y);
                MMA_BF16(c[mt][nt], al[mt][0], al[mt][1], al[mt][2], al[mt][3], f.x, f.y);
                MMA_BF16(c[mt][nt], ah[mt][0], ah[mt][1], ah[mt][2], ah[mt][3], f.z, f.w);
            }
        }
    }

    // Epilogue: rows m_base+mt*16+g (+8), cols nt*8 + 2t (+1) in zl/zr per cb
    float* base = (cb == 0) ? G_ZL : G_ZR;
#pragma unroll
    for (int mt = 0; mt < 2; mt++) {
#pragma unroll
        for (int nt = 0; nt < 8; nt++) {
            int colg = nt * 8 + 2 * t;
            size_t r0 = (size_t)(node0 + m_base + mt * 16 + g);
            *(float2*)&base[r0 * D_EMB + colg]       = make_float2(c[mt][nt][0], c[mt][nt][1]);
            *(float2*)&base[(r0 + 8) * D_EMB + colg] = make_float2(c[mt][nt][2], c[mt][nt][3]);
        }
    }
}

// ================== fused gather-aggregate + epilogue =========================
__global__ void gather_h_kernel(const float* __restrict__ b) {
    const int lane = threadIdx.x & 31;
    const int node = blockIdx.x * 8 + (threadIdx.x >> 5);
    if (node >= N_NODES) return;

    const int beg = g_off[node];
    const int deg = g_deg[node];
    const int end = beg + deg;

    const float2* zl2 = (const float2*)G_ZL;
    float2 s = make_float2(0.f, 0.f);

    int j = beg;
    for (; j + 4 <= end; j += 4) {
        int i0 = g_csr[j], i1 = g_csr[j + 1], i2 = g_csr[j + 2], i3 = g_csr[j + 3];
        float2 v0 = __ldg(&zl2[i0 * 32 + lane]);
        float2 v1 = __ldg(&zl2[i1 * 32 + lane]);
        float2 v2 = __ldg(&zl2[i2 * 32 + lane]);
        float2 v3 = __ldg(&zl2[i3 * 32 + lane]);
        s.x += (v0.x + v1.x) + (v2.x + v3.x);
        s.y += (v0.y + v1.y) + (v2.y + v3.y);
    }
    for (; j < end; j++) {
        float2 v = __ldg(&zl2[g_csr[j] * 32 + lane]);
        s.x += v.x; s.y += v.y;
    }

    const float inv = 1.0f / (float)max(deg, 1);
    const float2 zr = ((const float2*)G_ZR)[node * 32 + lane];
    float2 h;
    h.x = s.x * inv + __ldg(&b[lane * 2])     + zr.x;
    h.y = s.y * inv + __ldg(&b[lane * 2 + 1]) + zr.y;
    ((float2*)G_H)[node * 32 + lane] = h;
}

// ================== graph mean pool ==========================================
__global__ void pool_kernel() {
    __shared__ float red[256];
    const int g = blockIdx.x, tid = threadIdx.x;
    const int d = tid & 63, part = tid >> 6;
    const float* base = G_H + (size_t)g * NODES_PER_GRAPH * D_EMB;
    float s = 0.f;
    for (int n = part; n < NODES_PER_GRAPH; n += 4)
        s += base[n * D_EMB + d];
    red[tid] = s;
    __syncthreads();
    if (part == 0) {
        float t = red[d] + red[64 + d] + red[128 + d] + red[192 + d];
        g_pool[g * D_EMB + d] = t * (1.0f / NODES_PER_GRAPH);
    }
}

// ================== MLP head =================================================
__global__ void head_kernel(const float* __restrict__ fc1_W,
                            const float* __restrict__ fc1_b,
                            const float* __restrict__ fc2_W,
                            const float* __restrict__ fc2_b,
                            float* __restrict__ out) {
    __shared__ float gs[D_EMB];
    __shared__ float hs[D_HID];
    const int g = blockIdx.x, tid = threadIdx.x;
    if (tid < D_EMB) gs[tid] = g_pool[g * D_EMB + tid];
    __syncthreads();
    if (tid < D_HID) {
        float acc = fc1_b[tid];
        const float* w = fc1_W + (size_t)tid * D_EMB;
#pragma unroll
        for (int k = 0; k < D_EMB; k++) acc += gs[k] * w[k];
        hs[tid] = fmaxf(acc, 0.f);
    }
    __syncthreads();
    for (int a = tid; a < N_ACT; a += 256) {
        const float4* w = (const float4*)(fc2_W + (size_t)a * D_HID);
        float a0 = 0.f, a1 = 0.f, a2 = 0.f, a3 = 0.f;
#pragma unroll
        for (int k = 0; k < D_HID / 4; k++) {
            float4 wv = __ldg(&w[k]);
            a0 += wv.x * hs[4 * k + 0];
            a1 += wv.y * hs[4 * k + 1];
            a2 += wv.z * hs[4 * k + 2];
            a3 += wv.w * hs[4 * k + 3];
        }
        out[(size_t)g * N_ACT + a] = fc2_b[a] + (a0 + a1) + (a2 + a3);
    }
}

// ================== launch ===================================================
extern "C" void kernel_launch(void* const* d_in, const int* in_sizes, int n_in,
                              void* d_out, int out_size) {
    const float* x     = (const float*)d_in[0];
    const int*   ei    = (const int*)d_in[1];
    const float* W1l   = (const float*)d_in[2];
    const float* b1l   = (const float*)d_in[3];
    const float* W1r   = (const float*)d_in[4];
    const float* W2l   = (const float*)d_in[5];
    const float* b2l   = (const float*)d_in[6];
    const float* W2r   = (const float*)d_in[7];
    const float* fc1_W = (const float*)d_in[8];
    const float* fc1_b = (const float*)d_in[9];
    const float* fc2_W = (const float*)d_in[10];
    const float* fc2_b = (const float*)d_in[11];
    float* out = (float*)d_out;

    const int* src = ei;
    const int* dst = ei + N_EDGES;

    const int SMEM1 = 2 * 128 * (D_IN / 2 + 4) * 4;   // 69632 B
    const int SMEM2 = 2 * 128 * (D_EMB / 2 + 4) * 4;  // 36864 B
    cudaFuncSetAttribute(lin_tc_kernel<D_IN>,  cudaFuncAttributeMaxDynamicSharedMemorySize, SMEM1);
    cudaFuncSetAttribute(lin_tc_kernel<D_EMB>, cudaFuncAttributeMaxDynamicSharedMemorySize, SMEM2);

    // lin_tc<128> kept as 4th launch (profiler capture slot)
    deg_zero_kernel<<<N_NODES / 256, 256>>>();
    hist_kernel<<<2048, 256>>>(dst);
    wsplit_kernel<<<16, 256>>>(W1l, W1r, W2l, W2r);
    lin_tc_kernel<D_IN><<<N_NODES / 128, 256, SMEM1>>>(x);

    blocksum_kernel<<<SCAN_BLOCKS, 256>>>();
    scan_blk_kernel<<<1, SCAN_BLOCKS>>>();
    offsets_kernel<<<SCAN_BLOCKS, 256>>>();
    scatter_kernel<<<2048, 256>>>(src, dst);

    gather_h_kernel<<<N_NODES / 8, 256>>>(b1l);

    lin_tc_kernel<D_EMB><<<N_NODES / 128, 256, SMEM2>>>(nullptr);
    gather_h_kernel<<<N_NODES / 8, 256>>>(b2l);

    pool_kernel<<<N_GRAPHS, 256>>>();
    head_kernel<<<N_GRAPHS, 256>>>(fc1_W, fc1_b, fc2_W, fc2_b, out);
}

// round 9
// speedup vs baseline: 1.7272x; 1.0290x over previous
#include <cuda_runtime.h>
#include <cuda_bf16.h>
#include <cstdint>

#define N_NODES 131072
#define N_EDGES 2097152
#define N_GRAPHS 64
#define NODES_PER_GRAPH 2048
#define D_IN 128
#define D_EMB 64
#define D_HID 128
#define N_ACT 2048

#define SCAN_BLOCKS 512           // 512 * 256 = 131072

// ---------------- scratch (device globals) -----------------------------------
__device__ float4 g_zl4 [N_NODES * D_EMB / 4];   // in @ Wl.T (messages)
__device__ float4 g_zr4 [N_NODES * D_EMB / 4];   // in @ Wr.T (self term)
__device__ float4 g_h4  [N_NODES * D_EMB / 4];   // h1 then h2
__device__ float  g_pool[N_GRAPHS * D_EMB];

__device__ int g_deg [N_NODES];
__device__ int g_off [N_NODES];
__device__ int g_cur [N_NODES];
__device__ int g_csr [N_EDGES];
__device__ int g_blksum[SCAN_BLOCKS];
__device__ int g_blkoff[SCAN_BLOCKS];

// fragment-packed bf16 weights: index ((ks*4 + t)*128 + col)
// uint4 = { hi pair @ ks*8+t, hi pair @ ks*8+t+4, lo pair @ ks*8+t, lo pair @ ks*8+t+4 }
// col < 64 -> Wl output col, col >= 64 -> Wr output col-64
__device__ uint4 g_w1f[(128 / 16) * 4 * 128];   // 4096 entries, 64 KB
__device__ uint4 g_w2f[(64 / 16) * 4 * 128];    // 2048 entries, 32 KB

#define G_ZL  ((float*)g_zl4)
#define G_ZR  ((float*)g_zr4)
#define G_H   ((float*)g_h4)

// ---------------- bf16 helpers -------------------------------------------------
__device__ __forceinline__ uint32_t pack_bf16(__nv_bfloat16 a, __nv_bfloat16 b) {
    __nv_bfloat162 p = __halves2bfloat162(a, b);   // a in low half (element k)
    return *reinterpret_cast<uint32_t*>(&p);
}

__device__ __forceinline__ void split_pair(float v0, float v1,
                                           uint32_t& hi, uint32_t& lo) {
    __nv_bfloat16 h0 = __float2bfloat16_rn(v0);
    __nv_bfloat16 h1 = __float2bfloat16_rn(v1);
    __nv_bfloat16 l0 = __float2bfloat16_rn(v0 - __bfloat162float(h0));
    __nv_bfloat16 l1 = __float2bfloat16_rn(v1 - __bfloat162float(h1));
    hi = pack_bf16(h0, h1);
    lo = pack_bf16(l0, l1);
}

#define MMA_BF16(C, a0, a1, a2, a3, b0, b1)                                   \
    asm volatile(                                                             \
        "mma.sync.aligned.m16n8k16.row.col.f32.bf16.bf16.f32 "                \
        "{%0,%1,%2,%3}, {%4,%5,%6,%7}, {%8,%9}, {%0,%1,%2,%3};"               \
        : "+f"((C)[0]), "+f"((C)[1]), "+f"((C)[2]), "+f"((C)[3])              \
        : "r"(a0), "r"(a1), "r"(a2), "r"(a3), "r"(b0), "r"(b1))

// ================== CSR build =================================================
__global__ void deg_zero_kernel() {
    int i = blockIdx.x * blockDim.x + threadIdx.x;
    if (i < N_NODES) g_deg[i] = 0;
    if (i < N_GRAPHS * D_EMB) g_pool[i] = 0.f;
}

__global__ void hist_kernel(const int* __restrict__ dst) {
    int stride = gridDim.x * blockDim.x;
    for (int e = blockIdx.x * blockDim.x + threadIdx.x; e < N_EDGES; e += stride)
        atomicAdd(&g_deg[dst[e]], 1);
}

__global__ void blocksum_kernel() {
    __shared__ int red[256];
    int i = blockIdx.x * 256 + threadIdx.x;
    red[threadIdx.x] = g_deg[i];
    __syncthreads();
    for (int s = 128; s > 0; s >>= 1) {
        if (threadIdx.x < s) red[threadIdx.x] += red[threadIdx.x + s];
        __syncthreads();
    }
    if (threadIdx.x == 0) g_blksum[blockIdx.x] = red[0];
}

__global__ void scan_blk_kernel() {
    __shared__ int sm[SCAN_BLOCKS];
    int t = threadIdx.x;
    sm[t] = g_blksum[t];
    __syncthreads();
    for (int d = 1; d < SCAN_BLOCKS; d <<= 1) {
        int v = (t >= d) ? sm[t - d] : 0;
        __syncthreads();
        sm[t] += v;
        __syncthreads();
    }
    g_blkoff[t] = sm[t] - g_blksum[t];
}

__global__ void offsets_kernel() {
    __shared__ int sm[256];
    int i = blockIdx.x * 256 + threadIdx.x;
    int t = threadIdx.x;
    int d = g_deg[i];
    sm[t] = d;
    __syncthreads();
    for (int s = 1; s < 256; s <<= 1) {
        int v = (t >= s) ? sm[t - s] : 0;
        __syncthreads();
        sm[t] += v;
        __syncthreads();
    }
    int off = g_blkoff[blockIdx.x] + sm[t] - d;
    g_off[i] = off;
    g_cur[i] = off;
}

__global__ void scatter_kernel(const int* __restrict__ src,
                               const int* __restrict__ dst) {
    int stride = gridDim.x * blockDim.x;
    for (int e = blockIdx.x * blockDim.x + threadIdx.x; e < N_EDGES; e += stride) {
        int d = dst[e];
        int pos = atomicAdd(&g_cur[d], 1);
        g_csr[pos] = src[e];
    }
}

// ================== weight pre-split to fragment-packed uint4 (once) ==========
template <int K>
__device__ __forceinline__ uint4 make_wfrag(const float* __restrict__ Wrow,
                                            int ks, int t) {
    int p0 = ks * 8 + t;
    int p1 = ks * 8 + t + 4;
    uint4 f;
    uint32_t h0, l0, h1, l1;
    split_pair(Wrow[2 * p0], Wrow[2 * p0 + 1], h0, l0);
    split_pair(Wrow[2 * p1], Wrow[2 * p1 + 1], h1, l1);
    f.x = h0; f.y = h1; f.z = l0; f.w = l1;
    return f;
}

__global__ void wsplit_kernel(const float* __restrict__ W1l,
                              const float* __restrict__ W1r,
                              const float* __restrict__ W2l,
                              const float* __restrict__ W2r) {
    int i = blockIdx.x * blockDim.x + threadIdx.x;
    if (i < 8 * 4 * 128) {        // layer 1: ks<8
        int col = i & 127, tt = (i >> 7) & 3, ks = i >> 9;
        const float* Wrow = (col < 64) ? (W1l + col * 128) : (W1r + (col - 64) * 128);
        g_w1f[i] = make_wfrag<128>(Wrow, ks, tt);
    }
    if (i < 4 * 4 * 128) {        // layer 2: ks<4
        int col = i & 127, tt = (i >> 7) & 3, ks = i >> 9;
        const float* Wrow = (col < 64) ? (W2l + col * 64) : (W2r + (col - 64) * 64);
        g_w2f[i] = make_wfrag<64>(Wrow, ks, tt);
    }
}

// ================== tensor-core dual projection (3xBF16, m16n8k16) ============
// (R7 version — known good; tcgen05 unavailable on this toolchain target.)
template <int K>
__global__ void __launch_bounds__(256, 2) lin_tc_kernel(const float* __restrict__ in_param) {
    constexpr int SU = K / 2 + 4;
    extern __shared__ uint32_t sm[];
    uint32_t* Ah = sm;              // [128][SU]
    uint32_t* Al = Ah + 128 * SU;

    const float* in  = (K == D_EMB) ? G_H   : in_param;
    const uint4* Wf  = (K == D_EMB) ? g_w2f : g_w1f;

    const int tid = threadIdx.x;
    const int node0 = blockIdx.x * 128;

    const float4* inv = (const float4*)(in + (size_t)node0 * K);
    for (int idx = tid; idx < 128 * K / 4; idx += 256) {
        float4 v = inv[idx];
        int row = idx / (K / 4), w0 = (idx % (K / 4)) * 2;
        uint32_t h01, l01, h23, l23;
        split_pair(v.x, v.y, h01, l01);
        split_pair(v.z, v.w, h23, l23);
        Ah[row * SU + w0] = h01;  Ah[row * SU + w0 + 1] = h23;
        Al[row * SU + w0] = l01;  Al[row * SU + w0 + 1] = l23;
    }
    __syncthreads();

    const int warp = tid >> 5, lane = tid & 31;
    const int g = lane >> 2, t = lane & 3;
    const int m_base = (warp >> 1) * 32;
    const int cb     = (warp & 1) * 64;

    float c[2][8][4];
#pragma unroll
    for (int mt = 0; mt < 2; mt++)
#pragma unroll
        for (int nt = 0; nt < 8; nt++)
#pragma unroll
            for (int j = 0; j < 4; j++) c[mt][nt][j] = 0.f;

#pragma unroll
    for (int ks = 0; ks < K / 16; ks++) {
        const int kk = ks * 8 + t;
        uint32_t ah[2][4], al[2][4];
#pragma unroll
        for (int mt = 0; mt < 2; mt++) {
            int r0 = m_base + mt * 16 + g;
            ah[mt][0] = Ah[r0 * SU + kk];
            ah[mt][1] = Ah[(r0 + 8) * SU + kk];
            ah[mt][2] = Ah[r0 * SU + kk + 4];
            ah[mt][3] = Ah[(r0 + 8) * SU + kk + 4];
            al[mt][0] = Al[r0 * SU + kk];
            al[mt][1] = Al[(r0 + 8) * SU + kk];
            al[mt][2] = Al[r0 * SU + kk + 4];
            al[mt][3] = Al[(r0 + 8) * SU + kk + 4];
        }
        const uint4* wrow = Wf + (size_t)(ks * 4 + t) * 128 + cb + g;
#pragma unroll
        for (int nt = 0; nt < 8; nt++) {
            uint4 f = __ldg(wrow + nt * 8);
#pragma unroll
            for (int mt = 0; mt < 2; mt++) {
                MMA_BF16(c[mt][nt], ah[mt][0], ah[mt][1], ah[mt][2], ah[mt][3], f.x, f.y);
                MMA_BF16(c[mt][nt], al[mt][0], al[mt][1], al[mt][2], al[mt][3], f.x, f.y);
                MMA_BF16(c[mt][nt], ah[mt][0], ah[mt][1], ah[mt][2], ah[mt][3], f.z, f.w);
            }
        }
    }

    float* base = (cb == 0) ? G_ZL : G_ZR;
#pragma unroll
    for (int mt = 0; mt < 2; mt++) {
#pragma unroll
        for (int nt = 0; nt < 8; nt++) {
            int colg = nt * 8 + 2 * t;
            size_t r0 = (size_t)(node0 + m_base + mt * 16 + g);
            *(float2*)&base[r0 * D_EMB + colg]       = make_float2(c[mt][nt][0], c[mt][nt][1]);
            *(float2*)&base[(r0 + 8) * D_EMB + colg] = make_float2(c[mt][nt][2], c[mt][nt][3]);
        }
    }
}

// ================== fused gather-aggregate + epilogue (v2) =====================
// One warp per node. Lanes 0-15 process edge j (16 x LDG.128 covering 64 dims),
// lanes 16-31 process edge j+2 in the same iteration. Halves combined by shfl.
__global__ void gather_h_kernel(const float* __restrict__ b) {
    const int lane = threadIdx.x & 31;
    const int node = blockIdx.x * 8 + (threadIdx.x >> 5);
    const int half = lane >> 4;          // 0 or 1
    const int q    = lane & 15;          // float4 index within the 64-dim row

    const int beg = g_off[node];
    const int deg = g_deg[node];
    const int end = beg + deg;

    const float4* zl4 = (const float4*)G_ZL;
    float4 s = make_float4(0.f, 0.f, 0.f, 0.f);

    int j = beg + half;                  // this half's edge stream: j, j+2, j+4, ...
    for (; j + 2 < end; j += 4) {        // unroll 2 (edges j and j+2)
        int s0 = g_csr[j];
        int s1 = g_csr[j + 2];
        float4 v0 = __ldg(&zl4[(size_t)s0 * 16 + q]);
        float4 v1 = __ldg(&zl4[(size_t)s1 * 16 + q]);
        s.x += v0.x + v1.x;  s.y += v0.y + v1.y;
        s.z += v0.z + v1.z;  s.w += v0.w + v1.w;
    }
    for (; j < end; j += 2) {
        float4 v = __ldg(&zl4[(size_t)g_csr[j] * 16 + q]);
        s.x += v.x; s.y += v.y; s.z += v.z; s.w += v.w;
    }

    // combine the two halves (lane i += lane i+16)
    s.x += __shfl_down_sync(0xffffffffu, s.x, 16);
    s.y += __shfl_down_sync(0xffffffffu, s.y, 16);
    s.z += __shfl_down_sync(0xffffffffu, s.z, 16);
    s.w += __shfl_down_sync(0xffffffffu, s.w, 16);

    if (half == 0) {
        const float inv = 1.0f / (float)max(deg, 1);
        float4 zr = ((const float4*)G_ZR)[(size_t)node * 16 + q];
        float4 bb = __ldg(&((const float4*)b)[q]);
        float4 h;
        h.x = s.x * inv + bb.x + zr.x;
        h.y = s.y * inv + bb.y + zr.y;
        h.z = s.z * inv + bb.z + zr.z;
        h.w = s.w * inv + bb.w + zr.w;
        ((float4*)G_H)[(size_t)node * 16 + q] = h;
    }
}

// ================== graph mean pool (v2: 8 chunk-blocks per graph) ============
__global__ void pool_kernel() {
    __shared__ float red[256];
    const int g = blockIdx.x >> 3, chunk = blockIdx.x & 7;
    const int tid = threadIdx.x;
    const int d = tid & 63, part = tid >> 6;
    const float* base = G_H + ((size_t)g * NODES_PER_GRAPH + chunk * 256) * D_EMB;
    float s = 0.f;
    for (int n = part; n < 256; n += 4)
        s += base[n * D_EMB + d];
    red[tid] = s;
    __syncthreads();
    if (part == 0) {
        float t = red[d] + red[64 + d] + red[128 + d] + red[192 + d];
        atomicAdd(&g_pool[g * D_EMB + d], t);
    }
}

// ================== MLP head =================================================
__global__ void head_kernel(const float* __restrict__ fc1_W,
                            const float* __restrict__ fc1_b,
                            const float* __restrict__ fc2_W,
                            const float* __restrict__ fc2_b,
                            float* __restrict__ out) {
    __shared__ float gs[D_EMB];
    __shared__ float hs[D_HID];
    const int g = blockIdx.x, tid = threadIdx.x;
    if (tid < D_EMB) gs[tid] = g_pool[g * D_EMB + tid] * (1.0f / NODES_PER_GRAPH);
    __syncthreads();
    if (tid < D_HID) {
        float acc = fc1_b[tid];
        const float* w = fc1_W + (size_t)tid * D_EMB;
#pragma unroll
        for (int k = 0; k < D_EMB; k++) acc += gs[k] * w[k];
        hs[tid] = fmaxf(acc, 0.f);
    }
    __syncthreads();
    for (int a = tid; a < N_ACT; a += 256) {
        const float4* w = (const float4*)(fc2_W + (size_t)a * D_HID);
        float a0 = 0.f, a1 = 0.f, a2 = 0.f, a3 = 0.f;
#pragma unroll
        for (int k = 0; k < D_HID / 4; k++) {
            float4 wv = __ldg(&w[k]);
            a0 += wv.x * hs[4 * k + 0];
            a1 += wv.y * hs[4 * k + 1];
            a2 += wv.z * hs[4 * k + 2];
            a3 += wv.w * hs[4 * k + 3];
        }
        out[(size_t)g * N_ACT + a] = fc2_b[a] + (a0 + a1) + (a2 + a3);
    }
}

// ================== launch ===================================================
extern "C" void kernel_launch(void* const* d_in, const int* in_sizes, int n_in,
                              void* d_out, int out_size) {
    const float* x     = (const float*)d_in[0];
    const int*   ei    = (const int*)d_in[1];
    const float* W1l   = (const float*)d_in[2];
    const float* b1l   = (const float*)d_in[3];
    const float* W1r   = (const float*)d_in[4];
    const float* W2l   = (const float*)d_in[5];
    const float* b2l   = (const float*)d_in[6];
    const float* W2r   = (const float*)d_in[7];
    const float* fc1_W = (const float*)d_in[8];
    const float* fc1_b = (const float*)d_in[9];
    const float* fc2_W = (const float*)d_in[10];
    const float* fc2_b = (const float*)d_in[11];
    float* out = (float*)d_out;

    const int* src = ei;
    const int* dst = ei + N_EDGES;

    const int SMEM1 = 2 * 128 * (D_IN / 2 + 4) * 4;   // 69632 B
    const int SMEM2 = 2 * 128 * (D_EMB / 2 + 4) * 4;  // 36864 B
    cudaFuncSetAttribute(lin_tc_kernel<D_IN>,  cudaFuncAttributeMaxDynamicSharedMemorySize, SMEM1);
    cudaFuncSetAttribute(lin_tc_kernel<D_EMB>, cudaFuncAttributeMaxDynamicSharedMemorySize, SMEM2);

    // lin_tc<128> kept as 4th launch (profiler capture slot)
    deg_zero_kernel<<<N_NODES / 256, 256>>>();
    hist_kernel<<<2048, 256>>>(dst);
    wsplit_kernel<<<16, 256>>>(W1l, W1r, W2l, W2r);
    lin_tc_kernel<D_IN><<<N_NODES / 128, 256, SMEM1>>>(x);

    blocksum_kernel<<<SCAN_BLOCKS, 256>>>();
    scan_blk_kernel<<<1, SCAN_BLOCKS>>>();
    offsets_kernel<<<SCAN_BLOCKS, 256>>>();
    scatter_kernel<<<2048, 256>>>(src, dst);

    gather_h_kernel<<<N_NODES / 8, 256>>>(b1l);

    lin_tc_kernel<D_EMB><<<N_NODES / 128, 256, SMEM2>>>(nullptr);
    gather_h_kernel<<<N_NODES / 8, 256>>>(b2l);

    pool_kernel<<<N_GRAPHS * 8, 256>>>();
    head_kernel<<<N_GRAPHS, 256>>>(fc1_W, fc1_b, fc2_W, fc2_b, out);
}

// round 10
// speedup vs baseline: 1.7668x; 1.0229x over previous
#include <cuda_runtime.h>
#include <cuda_bf16.h>
#include <cstdint>

#define N_NODES 131072
#define N_EDGES 2097152
#define N_GRAPHS 64
#define NODES_PER_GRAPH 2048
#define D_IN 128
#define D_EMB 64
#define D_HID 128
#define N_ACT 2048

// ---------------- scratch (device globals) -----------------------------------
__device__ float4 g_zl4 [N_NODES * D_EMB / 4];   // in @ Wl.T (messages)
__device__ float4 g_zr4 [N_NODES * D_EMB / 4];   // in @ Wr.T (self term)
__device__ float4 g_h4  [N_NODES * D_EMB / 4];   // h1 then h2
__device__ float  g_pool[N_GRAPHS * D_EMB];

__device__ int g_deg [N_NODES];
__device__ int g_off [N_NODES];
__device__ int g_cur [N_NODES];
__device__ int g_csr [N_EDGES];
__device__ int g_total;

// fragment-packed bf16 weights: index ((ks*4 + t)*128 + col)
// uint4 = { hi pair @ ks*8+t, hi pair @ ks*8+t+4, lo pair @ ks*8+t, lo pair @ ks*8+t+4 }
__device__ uint4 g_w1f[(128 / 16) * 4 * 128];   // 4096 entries, 64 KB
__device__ uint4 g_w2f[(64 / 16) * 4 * 128];    // 2048 entries, 32 KB

#define G_ZL  ((float*)g_zl4)
#define G_ZR  ((float*)g_zr4)
#define G_H   ((float*)g_h4)

// ---------------- bf16 helpers -------------------------------------------------
__device__ __forceinline__ uint32_t pack_bf16(__nv_bfloat16 a, __nv_bfloat16 b) {
    __nv_bfloat162 p = __halves2bfloat162(a, b);   // a in low half (element k)
    return *reinterpret_cast<uint32_t*>(&p);
}

__device__ __forceinline__ void split_pair(float v0, float v1,
                                           uint32_t& hi, uint32_t& lo) {
    __nv_bfloat16 h0 = __float2bfloat16_rn(v0);
    __nv_bfloat16 h1 = __float2bfloat16_rn(v1);
    __nv_bfloat16 l0 = __float2bfloat16_rn(v0 - __bfloat162float(h0));
    __nv_bfloat16 l1 = __float2bfloat16_rn(v1 - __bfloat162float(h1));
    hi = pack_bf16(h0, h1);
    lo = pack_bf16(l0, l1);
}

#define MMA_BF16(C, a0, a1, a2, a3, b0, b1)                                   \
    asm volatile(                                                             \
        "mma.sync.aligned.m16n8k16.row.col.f32.bf16.bf16.f32 "                \
        "{%0,%1,%2,%3}, {%4,%5,%6,%7}, {%8,%9}, {%0,%1,%2,%3};"               \
        : "+f"((C)[0]), "+f"((C)[1]), "+f"((C)[2]), "+f"((C)[3])              \
        : "r"(a0), "r"(a1), "r"(a2), "r"(a3), "r"(b0), "r"(b1))

// ================== weight fragment builder ====================================
template <int K>
__device__ __forceinline__ uint4 make_wfrag(const float* __restrict__ Wrow,
                                            int ks, int t) {
    int p0 = ks * 8 + t;
    int p1 = ks * 8 + t + 4;
    uint4 f;
    uint32_t h0, l0, h1, l1;
    split_pair(Wrow[2 * p0], Wrow[2 * p0 + 1], h0, l0);
    split_pair(Wrow[2 * p1], Wrow[2 * p1 + 1], h1, l1);
    f.x = h0; f.y = h1; f.z = l0; f.w = l1;
    return f;
}

// ================== fused init: zero deg/pool/counter + wsplit =================
__global__ void init_kernel(const float* __restrict__ W1l,
                            const float* __restrict__ W1r,
                            const float* __restrict__ W2l,
                            const float* __restrict__ W2r) {
    int i = blockIdx.x * blockDim.x + threadIdx.x;
    if (i < N_NODES) g_deg[i] = 0;
    if (i < N_GRAPHS * D_EMB) g_pool[i] = 0.f;
    if (i == 0) g_total = 0;
    if (i < 8 * 4 * 128) {        // layer 1 frags
        int col = i & 127, tt = (i >> 7) & 3, ks = i >> 9;
        const float* Wrow = (col < 64) ? (W1l + col * 128) : (W1r + (col - 64) * 128);
        g_w1f[i] = make_wfrag<128>(Wrow, ks, tt);
    }
    if (i < 4 * 4 * 128) {        // layer 2 frags
        int col = i & 127, tt = (i >> 7) & 3, ks = i >> 9;
        const float* Wrow = (col < 64) ? (W2l + col * 64) : (W2r + (col - 64) * 64);
        g_w2f[i] = make_wfrag<64>(Wrow, ks, tt);
    }
}

// ================== CSR: hist -> alloc (warp-agg atomic) -> scatter ============
__global__ void hist_kernel(const int* __restrict__ dst) {
    int stride = gridDim.x * blockDim.x;
    for (int e = blockIdx.x * blockDim.x + threadIdx.x; e < N_EDGES; e += stride)
        atomicAdd(&g_deg[dst[e]], 1);
}

// segment offsets via warp-aggregated atomic bump (order-free, 1 atomic/warp)
__global__ void alloc_kernel() {
    int i = blockIdx.x * blockDim.x + threadIdx.x;
    int lane = threadIdx.x & 31;
    int d = g_deg[i];
    int p = d;                                   // inclusive warp scan
#pragma unroll
    for (int s = 1; s < 32; s <<= 1) {
        int v = __shfl_up_sync(0xffffffffu, p, s);
        if (lane >= s) p += v;
    }
    int wsum = __shfl_sync(0xffffffffu, p, 31);
    int base = 0;
    if (lane == 31) base = atomicAdd(&g_total, wsum);
    base = __shfl_sync(0xffffffffu, base, 31);
    int off = base + p - d;                      // exclusive within warp
    g_off[i] = off;
    g_cur[i] = off;
}

__global__ void scatter_kernel(const int* __restrict__ src,
                               const int* __restrict__ dst) {
    int stride = gridDim.x * blockDim.x;
    for (int e = blockIdx.x * blockDim.x + threadIdx.x; e < N_EDGES; e += stride) {
        int d = dst[e];
        int pos = atomicAdd(&g_cur[d], 1);
        g_csr[pos] = src[e];
    }
}

// ================== tensor-core dual projection (3xBF16, m16n8k16) ============
template <int K>
__global__ void __launch_bounds__(256, 2) lin_tc_kernel(const float* __restrict__ in_param) {
    constexpr int SU = K / 2 + 4;
    extern __shared__ uint32_t sm[];
    uint32_t* Ah = sm;              // [128][SU]
    uint32_t* Al = Ah + 128 * SU;

    const float* in  = (K == D_EMB) ? G_H   : in_param;
    const uint4* Wf  = (K == D_EMB) ? g_w2f : g_w1f;

    const int tid = threadIdx.x;
    const int node0 = blockIdx.x * 128;

    const float4* inv = (const float4*)(in + (size_t)node0 * K);
    for (int idx = tid; idx < 128 * K / 4; idx += 256) {
        float4 v = inv[idx];
        int row = idx / (K / 4), w0 = (idx % (K / 4)) * 2;
        uint32_t h01, l01, h23, l23;
        split_pair(v.x, v.y, h01, l01);
        split_pair(v.z, v.w, h23, l23);
        Ah[row * SU + w0] = h01;  Ah[row * SU + w0 + 1] = h23;
        Al[row * SU + w0] = l01;  Al[row * SU + w0 + 1] = l23;
    }
    __syncthreads();

    const int warp = tid >> 5, lane = tid & 31;
    const int g = lane >> 2, t = lane & 3;
    const int m_base = (warp >> 1) * 32;
    const int cb     = (warp & 1) * 64;

    float c[2][8][4];
#pragma unroll
    for (int mt = 0; mt < 2; mt++)
#pragma unroll
        for (int nt = 0; nt < 8; nt++)
#pragma unroll
            for (int j = 0; j < 4; j++) c[mt][nt][j] = 0.f;

#pragma unroll
    for (int ks = 0; ks < K / 16; ks++) {
        const int kk = ks * 8 + t;
        uint32_t ah[2][4], al[2][4];
#pragma unroll
        for (int mt = 0; mt < 2; mt++) {
            int r0 = m_base + mt * 16 + g;
            ah[mt][0] = Ah[r0 * SU + kk];
            ah[mt][1] = Ah[(r0 + 8) * SU + kk];
            ah[mt][2] = Ah[r0 * SU + kk + 4];
            ah[mt][3] = Ah[(r0 + 8) * SU + kk + 4];
            al[mt][0] = Al[r0 * SU + kk];
            al[mt][1] = Al[(r0 + 8) * SU + kk];
            al[mt][2] = Al[r0 * SU + kk + 4];
            al[mt][3] = Al[(r0 + 8) * SU + kk + 4];
        }
        const uint4* wrow = Wf + (size_t)(ks * 4 + t) * 128 + cb + g;
#pragma unroll
        for (int nt = 0; nt < 8; nt++) {
            uint4 f = __ldg(wrow + nt * 8);
#pragma unroll
            for (int mt = 0; mt < 2; mt++) {
                MMA_BF16(c[mt][nt], ah[mt][0], ah[mt][1], ah[mt][2], ah[mt][3], f.x, f.y);
                MMA_BF16(c[mt][nt], al[mt][0], al[mt][1], al[mt][2], al[mt][3], f.x, f.y);
                MMA_BF16(c[mt][nt], ah[mt][0], ah[mt][1], ah[mt][2], ah[mt][3], f.z, f.w);
            }
        }
    }

    float* base = (cb == 0) ? G_ZL : G_ZR;
#pragma unroll
    for (int mt = 0; mt < 2; mt++) {
#pragma unroll
        for (int nt = 0; nt < 8; nt++) {
            int colg = nt * 8 + 2 * t;
            size_t r0 = (size_t)(node0 + m_base + mt * 16 + g);
            *(float2*)&base[r0 * D_EMB + colg]       = make_float2(c[mt][nt][0], c[mt][nt][1]);
            *(float2*)&base[(r0 + 8) * D_EMB + colg] = make_float2(c[mt][nt][2], c[mt][nt][3]);
        }
    }
}

// ================== fused gather-aggregate + epilogue (v3: MLP 4/half) =========
__global__ void gather_h_kernel(const float* __restrict__ b) {
    const int lane = threadIdx.x & 31;
    const int node = blockIdx.x * 8 + (threadIdx.x >> 5);
    const int half = lane >> 4;          // 0 or 1
    const int q    = lane & 15;          // float4 index within the 64-dim row

    const int beg = g_off[node];
    const int deg = g_deg[node];
    const int end = beg + deg;

    const float4* zl4 = (const float4*)G_ZL;
    float4 s = make_float4(0.f, 0.f, 0.f, 0.f);

    int j = beg + half;                  // this half's stream: j, j+2, j+4, ...
    for (; j + 6 < end; j += 8) {        // 4 edges per half in flight
        int s0 = g_csr[j];
        int s1 = g_csr[j + 2];
        int s2 = g_csr[j + 4];
        int s3 = g_csr[j + 6];
        float4 v0 = __ldg(&zl4[(size_t)s0 * 16 + q]);
        float4 v1 = __ldg(&zl4[(size_t)s1 * 16 + q]);
        float4 v2 = __ldg(&zl4[(size_t)s2 * 16 + q]);
        float4 v3 = __ldg(&zl4[(size_t)s3 * 16 + q]);
        s.x += (v0.x + v1.x) + (v2.x + v3.x);
        s.y += (v0.y + v1.y) + (v2.y + v3.y);
        s.z += (v0.z + v1.z) + (v2.z + v3.z);
        s.w += (v0.w + v1.w) + (v2.w + v3.w);
    }
    for (; j < end; j += 2) {
        float4 v = __ldg(&zl4[(size_t)g_csr[j] * 16 + q]);
        s.x += v.x; s.y += v.y; s.z += v.z; s.w += v.w;
    }

    s.x += __shfl_down_sync(0xffffffffu, s.x, 16);
    s.y += __shfl_down_sync(0xffffffffu, s.y, 16);
    s.z += __shfl_down_sync(0xffffffffu, s.z, 16);
    s.w += __shfl_down_sync(0xffffffffu, s.w, 16);

    if (half == 0) {
        const float inv = 1.0f / (float)max(deg, 1);
        float4 zr = ((const float4*)G_ZR)[(size_t)node * 16 + q];
        float4 bb = __ldg(&((const float4*)b)[q]);
        float4 h;
        h.x = s.x * inv + bb.x + zr.x;
        h.y = s.y * inv + bb.y + zr.y;
        h.z = s.z * inv + bb.z + zr.z;
        h.w = s.w * inv + bb.w + zr.w;
        ((float4*)G_H)[(size_t)node * 16 + q] = h;
    }
}

// ================== graph mean pool (8 chunk-blocks per graph) =================
__global__ void pool_kernel() {
    __shared__ float red[256];
    const int g = blockIdx.x >> 3, chunk = blockIdx.x & 7;
    const int tid = threadIdx.x;
    const int d = tid & 63, part = tid >> 6;
    const float* base = G_H + ((size_t)g * NODES_PER_GRAPH + chunk * 256) * D_EMB;
    float s = 0.f;
    for (int n = part; n < 256; n += 4)
        s += base[n * D_EMB + d];
    red[tid] = s;
    __syncthreads();
    if (part == 0) {
        float t = red[d] + red[64 + d] + red[128 + d] + red[192 + d];
        atomicAdd(&g_pool[g * D_EMB + d], t);
    }
}

// ================== MLP head =================================================
__global__ void head_kernel(const float* __restrict__ fc1_W,
                            const float* __restrict__ fc1_b,
                            const float* __restrict__ fc2_W,
                            const float* __restrict__ fc2_b,
                            float* __restrict__ out) {
    __shared__ float gs[D_EMB];
    __shared__ float hs[D_HID];
    const int g = blockIdx.x, tid = threadIdx.x;
    if (tid < D_EMB) gs[tid] = g_pool[g * D_EMB + tid] * (1.0f / NODES_PER_GRAPH);
    __syncthreads();
    if (tid < D_HID) {
        float acc = fc1_b[tid];
        const float* w = fc1_W + (size_t)tid * D_EMB;
#pragma unroll
        for (int k = 0; k < D_EMB; k++) acc += gs[k] * w[k];
        hs[tid] = fmaxf(acc, 0.f);
    }
    __syncthreads();
    for (int a = tid; a < N_ACT; a += 256) {
        const float4* w = (const float4*)(fc2_W + (size_t)a * D_HID);
        float a0 = 0.f, a1 = 0.f, a2 = 0.f, a3 = 0.f;
#pragma unroll
        for (int k = 0; k < D_HID / 4; k++) {
            float4 wv = __ldg(&w[k]);
            a0 += wv.x * hs[4 * k + 0];
            a1 += wv.y * hs[4 * k + 1];
            a2 += wv.z * hs[4 * k + 2];
            a3 += wv.w * hs[4 * k + 3];
        }
        out[(size_t)g * N_ACT + a] = fc2_b[a] + (a0 + a1) + (a2 + a3);
    }
}

// ================== launch ===================================================
extern "C" void kernel_launch(void* const* d_in, const int* in_sizes, int n_in,
                              void* d_out, int out_size) {
    const float* x     = (const float*)d_in[0];
    const int*   ei    = (const int*)d_in[1];
    const float* W1l   = (const float*)d_in[2];
    const float* b1l   = (const float*)d_in[3];
    const float* W1r   = (const float*)d_in[4];
    const float* W2l   = (const float*)d_in[5];
    const float* b2l   = (const float*)d_in[6];
    const float* W2r   = (const float*)d_in[7];
    const float* fc1_W = (const float*)d_in[8];
    const float* fc1_b = (const float*)d_in[9];
    const float* fc2_W = (const float*)d_in[10];
    const float* fc2_b = (const float*)d_in[11];
    float* out = (float*)d_out;

    const int* src = ei;
    const int* dst = ei + N_EDGES;

    const int SMEM1 = 2 * 128 * (D_IN / 2 + 4) * 4;   // 69632 B
    const int SMEM2 = 2 * 128 * (D_EMB / 2 + 4) * 4;  // 36864 B
    cudaFuncSetAttribute(lin_tc_kernel<D_IN>,  cudaFuncAttributeMaxDynamicSharedMemorySize, SMEM1);
    cudaFuncSetAttribute(lin_tc_kernel<D_EMB>, cudaFuncAttributeMaxDynamicSharedMemorySize, SMEM2);

    // scatter_kernel is the 4th launch (profiler capture slot this round)
    init_kernel<<<N_NODES / 256, 256>>>(W1l, W1r, W2l, W2r);
    hist_kernel<<<2048, 256>>>(dst);
    alloc_kernel<<<N_NODES / 256, 256>>>();
    scatter_kernel<<<2048, 256>>>(src, dst);

    lin_tc_kernel<D_IN><<<N_NODES / 128, 256, SMEM1>>>(x);
    gather_h_kernel<<<N_NODES / 8, 256>>>(b1l);

    lin_tc_kernel<D_EMB><<<N_NODES / 128, 256, SMEM2>>>(nullptr);
    gather_h_kernel<<<N_NODES / 8, 256>>>(b2l);

    pool_kernel<<<N_GRAPHS * 8, 256>>>();
    head_kernel<<<N_GRAPHS, 256>>>(fc1_W, fc1_b, fc2_W, fc2_b, out);
}

// round 11
// speedup vs baseline: 1.7955x; 1.0162x over previous
#include <cuda_runtime.h>
#include <cuda_bf16.h>
#include <cstdint>

#define N_NODES 131072
#define N_EDGES 2097152
#define N_GRAPHS 64
#define NODES_PER_GRAPH 2048
#define D_IN 128
#define D_EMB 64
#define D_HID 128
#define N_ACT 2048

// ---------------- scratch (device globals) -----------------------------------
__device__ float4 g_zl4 [N_NODES * D_EMB / 4];   // in @ Wl.T (messages)
__device__ float4 g_zr4 [N_NODES * D_EMB / 4];   // in @ Wr.T (self term)
__device__ float4 g_h4  [N_NODES * D_EMB / 4];   // h1 (layer-2 output never stored)
__device__ float  g_pool[N_GRAPHS * D_EMB];

__device__ int g_deg [N_NODES];
__device__ int g_off [N_NODES];
__device__ int g_cur [N_NODES];
__device__ int g_csr [N_EDGES];
__device__ int g_total;

// fragment-packed bf16 weights: index ((ks*4 + t)*128 + col)
__device__ uint4 g_w1f[(128 / 16) * 4 * 128];   // 4096 entries, 64 KB
__device__ uint4 g_w2f[(64 / 16) * 4 * 128];    // 2048 entries, 32 KB

#define G_ZL  ((float*)g_zl4)
#define G_ZR  ((float*)g_zr4)
#define G_H   ((float*)g_h4)

// ---------------- bf16 helpers -------------------------------------------------
__device__ __forceinline__ uint32_t pack_bf16(__nv_bfloat16 a, __nv_bfloat16 b) {
    __nv_bfloat162 p = __halves2bfloat162(a, b);
    return *reinterpret_cast<uint32_t*>(&p);
}

__device__ __forceinline__ void split_pair(float v0, float v1,
                                           uint32_t& hi, uint32_t& lo) {
    __nv_bfloat16 h0 = __float2bfloat16_rn(v0);
    __nv_bfloat16 h1 = __float2bfloat16_rn(v1);
    __nv_bfloat16 l0 = __float2bfloat16_rn(v0 - __bfloat162float(h0));
    __nv_bfloat16 l1 = __float2bfloat16_rn(v1 - __bfloat162float(h1));
    hi = pack_bf16(h0, h1);
    lo = pack_bf16(l0, l1);
}

#define MMA_BF16(C, a0, a1, a2, a3, b0, b1)                                   \
    asm volatile(                                                             \
        "mma.sync.aligned.m16n8k16.row.col.f32.bf16.bf16.f32 "                \
        "{%0,%1,%2,%3}, {%4,%5,%6,%7}, {%8,%9}, {%0,%1,%2,%3};"               \
        : "+f"((C)[0]), "+f"((C)[1]), "+f"((C)[2]), "+f"((C)[3])              \
        : "r"(a0), "r"(a1), "r"(a2), "r"(a3), "r"(b0), "r"(b1))

// ================== weight fragment builder ====================================
template <int K>
__device__ __forceinline__ uint4 make_wfrag(const float* __restrict__ Wrow,
                                            int ks, int t) {
    int p0 = ks * 8 + t;
    int p1 = ks * 8 + t + 4;
    uint4 f;
    uint32_t h0, l0, h1, l1;
    split_pair(Wrow[2 * p0], Wrow[2 * p0 + 1], h0, l0);
    split_pair(Wrow[2 * p1], Wrow[2 * p1 + 1], h1, l1);
    f.x = h0; f.y = h1; f.z = l0; f.w = l1;
    return f;
}

// ================== fused init: zero deg/pool/counter + wsplit =================
__global__ void init_kernel(const float* __restrict__ W1l,
                            const float* __restrict__ W1r,
                            const float* __restrict__ W2l,
                            const float* __restrict__ W2r) {
    int i = blockIdx.x * blockDim.x + threadIdx.x;
    if (i < N_NODES) g_deg[i] = 0;
    if (i < N_GRAPHS * D_EMB) g_pool[i] = 0.f;
    if (i == 0) g_total = 0;
    if (i < 8 * 4 * 128) {
        int col = i & 127, tt = (i >> 7) & 3, ks = i >> 9;
        const float* Wrow = (col < 64) ? (W1l + col * 128) : (W1r + (col - 64) * 128);
        g_w1f[i] = make_wfrag<128>(Wrow, ks, tt);
    }
    if (i < 4 * 4 * 128) {
        int col = i & 127, tt = (i >> 7) & 3, ks = i >> 9;
        const float* Wrow = (col < 64) ? (W2l + col * 64) : (W2r + (col - 64) * 64);
        g_w2f[i] = make_wfrag<64>(Wrow, ks, tt);
    }
}

// ================== CSR: hist -> alloc (warp-agg atomic) -> scatter ============
__global__ void hist_kernel(const int* __restrict__ dst) {
    int stride = gridDim.x * blockDim.x;
    for (int e = blockIdx.x * blockDim.x + threadIdx.x; e < N_EDGES; e += stride)
        atomicAdd(&g_deg[dst[e]], 1);
}

__global__ void alloc_kernel() {
    int i = blockIdx.x * blockDim.x + threadIdx.x;
    int lane = threadIdx.x & 31;
    int d = g_deg[i];
    int p = d;
#pragma unroll
    for (int s = 1; s < 32; s <<= 1) {
        int v = __shfl_up_sync(0xffffffffu, p, s);
        if (lane >= s) p += v;
    }
    int wsum = __shfl_sync(0xffffffffu, p, 31);
    int base = 0;
    if (lane == 31) base = atomicAdd(&g_total, wsum);
    base = __shfl_sync(0xffffffffu, base, 31);
    int off = base + p - d;
    g_off[i] = off;
    g_cur[i] = off;
}

__global__ void scatter_kernel(const int* __restrict__ src,
                               const int* __restrict__ dst) {
    int stride = gridDim.x * blockDim.x;
    for (int e = blockIdx.x * blockDim.x + threadIdx.x; e < N_EDGES; e += stride) {
        int d = dst[e];
        int pos = atomicAdd(&g_cur[d], 1);
        g_csr[pos] = src[e];
    }
}

// ================== tensor-core dual projection (3xBF16, m16n8k16) ============
template <int K>
__global__ void __launch_bounds__(256, 2) lin_tc_kernel(const float* __restrict__ in_param) {
    constexpr int SU = K / 2 + 4;
    extern __shared__ uint32_t sm[];
    uint32_t* Ah = sm;              // [128][SU]
    uint32_t* Al = Ah + 128 * SU;

    const float* in  = (K == D_EMB) ? G_H   : in_param;
    const uint4* Wf  = (K == D_EMB) ? g_w2f : g_w1f;

    const int tid = threadIdx.x;
    const int node0 = blockIdx.x * 128;

    const float4* inv = (const float4*)(in + (size_t)node0 * K);
    for (int idx = tid; idx < 128 * K / 4; idx += 256) {
        float4 v = inv[idx];
        int row = idx / (K / 4), w0 = (idx % (K / 4)) * 2;
        uint32_t h01, l01, h23, l23;
        split_pair(v.x, v.y, h01, l01);
        split_pair(v.z, v.w, h23, l23);
        Ah[row * SU + w0] = h01;  Ah[row * SU + w0 + 1] = h23;
        Al[row * SU + w0] = l01;  Al[row * SU + w0 + 1] = l23;
    }
    __syncthreads();

    const int warp = tid >> 5, lane = tid & 31;
    const int g = lane >> 2, t = lane & 3;
    const int m_base = (warp >> 1) * 32;
    const int cb     = (warp & 1) * 64;

    float c[2][8][4];
#pragma unroll
    for (int mt = 0; mt < 2; mt++)
#pragma unroll
        for (int nt = 0; nt < 8; nt++)
#pragma unroll
            for (int j = 0; j < 4; j++) c[mt][nt][j] = 0.f;

#pragma unroll
    for (int ks = 0; ks < K / 16; ks++) {
        const int kk = ks * 8 + t;
        uint32_t ah[2][4], al[2][4];
#pragma unroll
        for (int mt = 0; mt < 2; mt++) {
            int r0 = m_base + mt * 16 + g;
            ah[mt][0] = Ah[r0 * SU + kk];
            ah[mt][1] = Ah[(r0 + 8) * SU + kk];
            ah[mt][2] = Ah[r0 * SU + kk + 4];
            ah[mt][3] = Ah[(r0 + 8) * SU + kk + 4];
            al[mt][0] = Al[r0 * SU + kk];
            al[mt][1] = Al[(r0 + 8) * SU + kk];
            al[mt][2] = Al[r0 * SU + kk + 4];
            al[mt][3] = Al[(r0 + 8) * SU + kk + 4];
        }
        const uint4* wrow = Wf + (size_t)(ks * 4 + t) * 128 + cb + g;
#pragma unroll
        for (int nt = 0; nt < 8; nt++) {
            uint4 f = __ldg(wrow + nt * 8);
#pragma unroll
            for (int mt = 0; mt < 2; mt++) {
                MMA_BF16(c[mt][nt], ah[mt][0], ah[mt][1], ah[mt][2], ah[mt][3], f.x, f.y);
                MMA_BF16(c[mt][nt], al[mt][0], al[mt][1], al[mt][2], al[mt][3], f.x, f.y);
                MMA_BF16(c[mt][nt], ah[mt][0], ah[mt][1], ah[mt][2], ah[mt][3], f.z, f.w);
            }
        }
    }

    float* base = (cb == 0) ? G_ZL : G_ZR;
#pragma unroll
    for (int mt = 0; mt < 2; mt++) {
#pragma unroll
        for (int nt = 0; nt < 8; nt++) {
            int colg = nt * 8 + 2 * t;
            size_t r0 = (size_t)(node0 + m_base + mt * 16 + g);
            *(float2*)&base[r0 * D_EMB + colg]       = make_float2(c[mt][nt][0], c[mt][nt][1]);
            *(float2*)&base[(r0 + 8) * D_EMB + colg] = make_float2(c[mt][nt][2], c[mt][nt][3]);
        }
    }
}

// ================== fused gather-aggregate + epilogue (v4) =====================
// One warp per node; lanes split into 2 halves streaming alternate edges with
// 8 rows in flight each. FUSE_POOL: layer-2 path skips writing G_H and instead
// block-reduces the 8 nodes' h into g_pool (block never straddles a graph).
template <bool FUSE_POOL>
__global__ void gather_h_kernel(const float* __restrict__ b) {
    const int lane = threadIdx.x & 31;
    const int wrp  = threadIdx.x >> 5;
    const int node = blockIdx.x * 8 + wrp;
    const int half = lane >> 4;          // 0 or 1
    const int q    = lane & 15;          // float4 index within the 64-dim row

    const int beg = g_off[node];
    const int deg = g_deg[node];
    const int end = beg + deg;

    const float4* zl4 = (const float4*)G_ZL;
    float4 s = make_float4(0.f, 0.f, 0.f, 0.f);

    int j = beg + half;                  // this half's stream: j, j+2, ...
    for (; j + 14 < end; j += 16) {      // 8 edges per half in flight
        int e0 = g_csr[j],      e1 = g_csr[j + 2],  e2 = g_csr[j + 4],  e3 = g_csr[j + 6];
        int e4 = g_csr[j + 8],  e5 = g_csr[j + 10], e6 = g_csr[j + 12], e7 = g_csr[j + 14];
        float4 v0 = __ldg(&zl4[(size_t)e0 * 16 + q]);
        float4 v1 = __ldg(&zl4[(size_t)e1 * 16 + q]);
        float4 v2 = __ldg(&zl4[(size_t)e2 * 16 + q]);
        float4 v3 = __ldg(&zl4[(size_t)e3 * 16 + q]);
        float4 v4 = __ldg(&zl4[(size_t)e4 * 16 + q]);
        float4 v5 = __ldg(&zl4[(size_t)e5 * 16 + q]);
        float4 v6 = __ldg(&zl4[(size_t)e6 * 16 + q]);
        float4 v7 = __ldg(&zl4[(size_t)e7 * 16 + q]);
        s.x += ((v0.x + v1.x) + (v2.x + v3.x)) + ((v4.x + v5.x) + (v6.x + v7.x));
        s.y += ((v0.y + v1.y) + (v2.y + v3.y)) + ((v4.y + v5.y) + (v6.y + v7.y));
        s.z += ((v0.z + v1.z) + (v2.z + v3.z)) + ((v4.z + v5.z) + (v6.z + v7.z));
        s.w += ((v0.w + v1.w) + (v2.w + v3.w)) + ((v4.w + v5.w) + (v6.w + v7.w));
    }
    for (; j < end; j += 2) {
        float4 v = __ldg(&zl4[(size_t)g_csr[j] * 16 + q]);
        s.x += v.x; s.y += v.y; s.z += v.z; s.w += v.w;
    }

    s.x += __shfl_down_sync(0xffffffffu, s.x, 16);
    s.y += __shfl_down_sync(0xffffffffu, s.y, 16);
    s.z += __shfl_down_sync(0xffffffffu, s.z, 16);
    s.w += __shfl_down_sync(0xffffffffu, s.w, 16);

    float4 h = make_float4(0.f, 0.f, 0.f, 0.f);
    if (half == 0) {
        const float inv = 1.0f / (float)max(deg, 1);
        float4 zr = ((const float4*)G_ZR)[(size_t)node * 16 + q];
        float4 bb = __ldg(&((const float4*)b)[q]);
        h.x = s.x * inv + bb.x + zr.x;
        h.y = s.y * inv + bb.y + zr.y;
        h.z = s.z * inv + bb.z + zr.z;
        h.w = s.w * inv + bb.w + zr.w;
        if (!FUSE_POOL)
            ((float4*)G_H)[(size_t)node * 16 + q] = h;
    }

    if (FUSE_POOL) {
        // reduce the block's 8 node-vectors into one per-graph partial
        __shared__ float4 red[8][16];
        if (half == 0) red[wrp][q] = h;
        __syncthreads();
        if (threadIdx.x < 64) {
            const int qq = threadIdx.x >> 2, comp = threadIdx.x & 3;
            float sum = 0.f;
#pragma unroll
            for (int w = 0; w < 8; w++) {
                float4 v = red[w][qq];
                sum += (comp == 0) ? v.x : (comp == 1) ? v.y : (comp == 2) ? v.z : v.w;
            }
            const int g = (blockIdx.x * 8) / NODES_PER_GRAPH;
            atomicAdd(&g_pool[g * D_EMB + qq * 4 + comp], sum);
        }
    }
}

// ================== MLP head =================================================
__global__ void head_kernel(const float* __restrict__ fc1_W,
                            const float* __restrict__ fc1_b,
                            const float* __restrict__ fc2_W,
                            const float* __restrict__ fc2_b,
                            float* __restrict__ out) {
    __shared__ float gs[D_EMB];
    __shared__ float hs[D_HID];
    const int g = blockIdx.x, tid = threadIdx.x;
    if (tid < D_EMB) gs[tid] = g_pool[g * D_EMB + tid] * (1.0f / NODES_PER_GRAPH);
    __syncthreads();
    if (tid < D_HID) {
        float acc = fc1_b[tid];
        const float* w = fc1_W + (size_t)tid * D_EMB;
#pragma unroll
        for (int k = 0; k < D_EMB; k++) acc += gs[k] * w[k];
        hs[tid] = fmaxf(acc, 0.f);
    }
    __syncthreads();
    for (int a = tid; a < N_ACT; a += 256) {
        const float4* w = (const float4*)(fc2_W + (size_t)a * D_HID);
        float a0 = 0.f, a1 = 0.f, a2 = 0.f, a3 = 0.f;
#pragma unroll
        for (int k = 0; k < D_HID / 4; k++) {
            float4 wv = __ldg(&w[k]);
            a0 += wv.x * hs[4 * k + 0];
            a1 += wv.y * hs[4 * k + 1];
            a2 += wv.z * hs[4 * k + 2];
            a3 += wv.w * hs[4 * k + 3];
        }
        out[(size_t)g * N_ACT + a] = fc2_b[a] + (a0 + a1) + (a2 + a3);
    }
}

// ================== launch ===================================================
extern "C" void kernel_launch(void* const* d_in, const int* in_sizes, int n_in,
                              void* d_out, int out_size) {
    const float* x     = (const float*)d_in[0];
    const int*   ei    = (const int*)d_in[1];
    const float* W1l   = (const float*)d_in[2];
    const float* b1l   = (const float*)d_in[3];
    const float* W1r   = (const float*)d_in[4];
    const float* W2l   = (const float*)d_in[5];
    const float* b2l   = (const float*)d_in[6];
    const float* W2r   = (const float*)d_in[7];
    const float* fc1_W = (const float*)d_in[8];
    const float* fc1_b = (const float*)d_in[9];
    const float* fc2_W = (const float*)d_in[10];
    const float* fc2_b = (const float*)d_in[11];
    float* out = (float*)d_out;

    const int* src = ei;
    const int* dst = ei + N_EDGES;

    const int SMEM1 = 2 * 128 * (D_IN / 2 + 4) * 4;   // 69632 B
    const int SMEM2 = 2 * 128 * (D_EMB / 2 + 4) * 4;  // 36864 B
    cudaFuncSetAttribute(lin_tc_kernel<D_IN>,  cudaFuncAttributeMaxDynamicSharedMemorySize, SMEM1);
    cudaFuncSetAttribute(lin_tc_kernel<D_EMB>, cudaFuncAttributeMaxDynamicSharedMemorySize, SMEM2);

    init_kernel<<<N_NODES / 256, 256>>>(W1l, W1r, W2l, W2r);
    hist_kernel<<<2048, 256>>>(dst);
    alloc_kernel<<<N_NODES / 256, 256>>>();
    scatter_kernel<<<2048, 256>>>(src, dst);      // profiler slot #4 (control)

    lin_tc_kernel<D_IN><<<N_NODES / 128, 256, SMEM1>>>(x);
    gather_h_kernel<false><<<N_NODES / 8, 256>>>(b1l);

    lin_tc_kernel<D_EMB><<<N_NODES / 128, 256, SMEM2>>>(nullptr);
    gather_h_kernel<true><<<N_NODES / 8, 256>>>(b2l);

    head_kernel<<<N_GRAPHS, 256>>>(fc1_W, fc1_b, fc2_W, fc2_b, out);
}

// round 12
// speedup vs baseline: 2.0886x; 1.1633x over previous
#include <cuda_runtime.h>
#include <cuda_bf16.h>
#include <cstdint>

#define N_NODES 131072
#define N_EDGES 2097152
#define N_GRAPHS 64
#define NODES_PER_GRAPH 2048
#define D_IN 128
#define D_EMB 64
#define D_HID 128
#define N_ACT 2048

// ---------------- scratch (device globals) -----------------------------------
__device__ uint32_t g_zlb [N_NODES * 32];        // zl as packed bf16 pairs, 128B/row
__device__ float4   g_zr4 [N_NODES * D_EMB / 4]; // in @ Wr.T (self term, f32)
__device__ float4   g_h4  [N_NODES * D_EMB / 4]; // h1 (layer-2 h never stored)
__device__ float    g_pool[N_GRAPHS * D_EMB];

__device__ int g_deg [N_NODES];
__device__ int g_off [N_NODES];
__device__ int g_cur [N_NODES];
__device__ int g_csr [N_EDGES];
__device__ int g_total;

// fragment-packed bf16 weights: index ((ks*4 + t)*128 + col)
__device__ uint4 g_w1f[(128 / 16) * 4 * 128];   // 4096 entries, 64 KB
__device__ uint4 g_w2f[(64 / 16) * 4 * 128];    // 2048 entries, 32 KB

#define G_ZR  ((float*)g_zr4)
#define G_H   ((float*)g_h4)

// ---------------- bf16 helpers -------------------------------------------------
__device__ __forceinline__ uint32_t pack_bf16(__nv_bfloat16 a, __nv_bfloat16 b) {
    __nv_bfloat162 p = __halves2bfloat162(a, b);   // a = low half (even dim)
    return *reinterpret_cast<uint32_t*>(&p);
}

__device__ __forceinline__ void split_pair(float v0, float v1,
                                           uint32_t& hi, uint32_t& lo) {
    __nv_bfloat16 h0 = __float2bfloat16_rn(v0);
    __nv_bfloat16 h1 = __float2bfloat16_rn(v1);
    __nv_bfloat16 l0 = __float2bfloat16_rn(v0 - __bfloat162float(h0));
    __nv_bfloat16 l1 = __float2bfloat16_rn(v1 - __bfloat162float(h1));
    hi = pack_bf16(h0, h1);
    lo = pack_bf16(l0, l1);
}

#define MMA_BF16(C, a0, a1, a2, a3, b0, b1)                                   \
    asm volatile(                                                             \
        "mma.sync.aligned.m16n8k16.row.col.f32.bf16.bf16.f32 "                \
        "{%0,%1,%2,%3}, {%4,%5,%6,%7}, {%8,%9}, {%0,%1,%2,%3};"               \
        : "+f"((C)[0]), "+f"((C)[1]), "+f"((C)[2]), "+f"((C)[3])              \
        : "r"(a0), "r"(a1), "r"(a2), "r"(a3), "r"(b0), "r"(b1))

// unpack-accumulate: 1 uint4 = 8 bf16 dims -> 8 f32 accumulators
__device__ __forceinline__ void acc8(float* a, uint4 u) {
    a[0] += __uint_as_float(u.x << 16);
    a[1] += __uint_as_float(u.x & 0xffff0000u);
    a[2] += __uint_as_float(u.y << 16);
    a[3] += __uint_as_float(u.y & 0xffff0000u);
    a[4] += __uint_as_float(u.z << 16);
    a[5] += __uint_as_float(u.z & 0xffff0000u);
    a[6] += __uint_as_float(u.w << 16);
    a[7] += __uint_as_float(u.w & 0xffff0000u);
}

// ================== weight fragment builder ====================================
template <int K>
__device__ __forceinline__ uint4 make_wfrag(const float* __restrict__ Wrow,
                                            int ks, int t) {
    int p0 = ks * 8 + t;
    int p1 = ks * 8 + t + 4;
    uint4 f;
    uint32_t h0, l0, h1, l1;
    split_pair(Wrow[2 * p0], Wrow[2 * p0 + 1], h0, l0);
    split_pair(Wrow[2 * p1], Wrow[2 * p1 + 1], h1, l1);
    f.x = h0; f.y = h1; f.z = l0; f.w = l1;
    return f;
}

// ================== fused init: zero deg/pool/counter + wsplit =================
__global__ void init_kernel(const float* __restrict__ W1l,
                            const float* __restrict__ W1r,
                            const float* __restrict__ W2l,
                            const float* __restrict__ W2r) {
    int i = blockIdx.x * blockDim.x + threadIdx.x;
    if (i < N_NODES) g_deg[i] = 0;
    if (i < N_GRAPHS * D_EMB) g_pool[i] = 0.f;
    if (i == 0) g_total = 0;
    if (i < 8 * 4 * 128) {
        int col = i & 127, tt = (i >> 7) & 3, ks = i >> 9;
        const float* Wrow = (col < 64) ? (W1l + col * 128) : (W1r + (col - 64) * 128);
        g_w1f[i] = make_wfrag<128>(Wrow, ks, tt);
    }
    if (i < 4 * 4 * 128) {
        int col = i & 127, tt = (i >> 7) & 3, ks = i >> 9;
        const float* Wrow = (col < 64) ? (W2l + col * 64) : (W2r + (col - 64) * 64);
        g_w2f[i] = make_wfrag<64>(Wrow, ks, tt);
    }
}

// ================== CSR: hist -> alloc (warp-agg atomic) -> scatter ============
__global__ void hist_kernel(const int* __restrict__ dst) {
    int stride = gridDim.x * blockDim.x;
    for (int e = blockIdx.x * blockDim.x + threadIdx.x; e < N_EDGES; e += stride)
        atomicAdd(&g_deg[dst[e]], 1);
}

__global__ void alloc_kernel() {
    int i = blockIdx.x * blockDim.x + threadIdx.x;
    int lane = threadIdx.x & 31;
    int d = g_deg[i];
    int p = d;
#pragma unroll
    for (int s = 1; s < 32; s <<= 1) {
        int v = __shfl_up_sync(0xffffffffu, p, s);
        if (lane >= s) p += v;
    }
    int wsum = __shfl_sync(0xffffffffu, p, 31);
    int base = 0;
    if (lane == 31) base = atomicAdd(&g_total, wsum);
    base = __shfl_sync(0xffffffffu, base, 31);
    int off = base + p - d;
    g_off[i] = off;
    g_cur[i] = off;
}

__global__ void scatter_kernel(const int* __restrict__ src,
                               const int* __restrict__ dst) {
    int stride = gridDim.x * blockDim.x;
    for (int e = blockIdx.x * blockDim.x + threadIdx.x; e < N_EDGES; e += stride) {
        int d = dst[e];
        int pos = atomicAdd(&g_cur[d], 1);
        g_csr[pos] = src[e];
    }
}

// ================== tensor-core dual projection (3xBF16, m16n8k16) ============
// zl half written as PACKED BF16 (messages); zr half stays f32.
template <int K>
__global__ void __launch_bounds__(256, 2) lin_tc_kernel(const float* __restrict__ in_param) {
    constexpr int SU = K / 2 + 4;
    extern __shared__ uint32_t sm[];
    uint32_t* Ah = sm;              // [128][SU]
    uint32_t* Al = Ah + 128 * SU;

    const float* in  = (K == D_EMB) ? G_H   : in_param;
    const uint4* Wf  = (K == D_EMB) ? g_w2f : g_w1f;

    const int tid = threadIdx.x;
    const int node0 = blockIdx.x * 128;

    const float4* inv = (const float4*)(in + (size_t)node0 * K);
    for (int idx = tid; idx < 128 * K / 4; idx += 256) {
        float4 v = inv[idx];
        int row = idx / (K / 4), w0 = (idx % (K / 4)) * 2;
        uint32_t h01, l01, h23, l23;
        split_pair(v.x, v.y, h01, l01);
        split_pair(v.z, v.w, h23, l23);
        Ah[row * SU + w0] = h01;  Ah[row * SU + w0 + 1] = h23;
        Al[row * SU + w0] = l01;  Al[row * SU + w0 + 1] = l23;
    }
    __syncthreads();

    const int warp = tid >> 5, lane = tid & 31;
    const int g = lane >> 2, t = lane & 3;
    const int m_base = (warp >> 1) * 32;
    const int cb     = (warp & 1) * 64;

    float c[2][8][4];
#pragma unroll
    for (int mt = 0; mt < 2; mt++)
#pragma unroll
        for (int nt = 0; nt < 8; nt++)
#pragma unroll
            for (int j = 0; j < 4; j++) c[mt][nt][j] = 0.f;

#pragma unroll
    for (int ks = 0; ks < K / 16; ks++) {
        const int kk = ks * 8 + t;
        uint32_t ah[2][4], al[2][4];
#pragma unroll
        for (int mt = 0; mt < 2; mt++) {
            int r0 = m_base + mt * 16 + g;
            ah[mt][0] = Ah[r0 * SU + kk];
            ah[mt][1] = Ah[(r0 + 8) * SU + kk];
            ah[mt][2] = Ah[r0 * SU + kk + 4];
            ah[mt][3] = Ah[(r0 + 8) * SU + kk + 4];
            al[mt][0] = Al[r0 * SU + kk];
            al[mt][1] = Al[(r0 + 8) * SU + kk];
            al[mt][2] = Al[r0 * SU + kk + 4];
            al[mt][3] = Al[(r0 + 8) * SU + kk + 4];
        }
        const uint4* wrow = Wf + (size_t)(ks * 4 + t) * 128 + cb + g;
#pragma unroll
        for (int nt = 0; nt < 8; nt++) {
            uint4 f = __ldg(wrow + nt * 8);
#pragma unroll
            for (int mt = 0; mt < 2; mt++) {
                MMA_BF16(c[mt][nt], ah[mt][0], ah[mt][1], ah[mt][2], ah[mt][3], f.x, f.y);
                MMA_BF16(c[mt][nt], al[mt][0], al[mt][1], al[mt][2], al[mt][3], f.x, f.y);
                MMA_BF16(c[mt][nt], ah[mt][0], ah[mt][1], ah[mt][2], ah[mt][3], f.z, f.w);
            }
        }
    }

    if (cb == 0) {
        // zl -> packed bf16 message rows (uint32 index i holds dims 2i, 2i+1)
#pragma unroll
        for (int mt = 0; mt < 2; mt++) {
#pragma unroll
            for (int nt = 0; nt < 8; nt++) {
                uint32_t p0 = pack_bf16(__float2bfloat16_rn(c[mt][nt][0]),
                                        __float2bfloat16_rn(c[mt][nt][1]));
                uint32_t p1 = pack_bf16(__float2bfloat16_rn(c[mt][nt][2]),
                                        __float2bfloat16_rn(c[mt][nt][3]));
                size_t r0 = (size_t)(node0 + m_base + mt * 16 + g);
                g_zlb[r0 * 32 + nt * 4 + t]       = p0;
                g_zlb[(r0 + 8) * 32 + nt * 4 + t] = p1;
            }
        }
    } else {
#pragma unroll
        for (int mt = 0; mt < 2; mt++) {
#pragma unroll
            for (int nt = 0; nt < 8; nt++) {
                int colg = nt * 8 + 2 * t;
                size_t r0 = (size_t)(node0 + m_base + mt * 16 + g);
                *(float2*)&G_ZR[r0 * D_EMB + colg]       = make_float2(c[mt][nt][0], c[mt][nt][1]);
                *(float2*)&G_ZR[(r0 + 8) * D_EMB + colg] = make_float2(c[mt][nt][2], c[mt][nt][3]);
            }
        }
    }
}

// ================== fused gather-aggregate + epilogue (v5: bf16 messages) ======
// One warp per node; 4 streams of 8 lanes. Each stream handles every 4th edge;
// a lane loads uint4 = 8 bf16 dims (1 L2 line per edge), accumulates f32.
template <bool FUSE_POOL>
__global__ void gather_h_kernel(const float* __restrict__ b) {
    const int lane = threadIdx.x & 31;
    const int wrp  = threadIdx.x >> 5;
    const int node = blockIdx.x * 8 + wrp;
    const int strm = lane >> 3;          // 0..3
    const int q    = lane & 7;           // uint4 index within the 128B row

    const int beg = g_off[node];
    const int deg = g_deg[node];
    const int end = beg + deg;

    const uint4* zlb = (const uint4*)g_zlb;
    float a[8];
#pragma unroll
    for (int i = 0; i < 8; i++) a[i] = 0.f;

    int j = beg + strm;                  // this stream: j, j+4, j+8, ...
    for (; j + 12 < end; j += 16) {      // 4 edges per stream in flight
        int e0 = g_csr[j], e1 = g_csr[j + 4], e2 = g_csr[j + 8], e3 = g_csr[j + 12];
        uint4 u0 = __ldg(&zlb[(size_t)e0 * 8 + q]);
        uint4 u1 = __ldg(&zlb[(size_t)e1 * 8 + q]);
        uint4 u2 = __ldg(&zlb[(size_t)e2 * 8 + q]);
        uint4 u3 = __ldg(&zlb[(size_t)e3 * 8 + q]);
        acc8(a, u0); acc8(a, u1); acc8(a, u2); acc8(a, u3);
    }
    for (; j < end; j += 4) {
        uint4 u = __ldg(&zlb[(size_t)g_csr[j] * 8 + q]);
        acc8(a, u);
    }

    // combine the 4 streams: lane l += lane l+16, then += lane l+8
#pragma unroll
    for (int i = 0; i < 8; i++) {
        a[i] += __shfl_down_sync(0xffffffffu, a[i], 16);
        a[i] += __shfl_down_sync(0xffffffffu, a[i], 8);
    }

    float4 h0, h1;
    if (strm == 0) {                     // lanes 0-7 hold dims q*8 .. q*8+7
        const float inv = 1.0f / (float)max(deg, 1);
        float4 zr0 = ((const float4*)G_ZR)[(size_t)node * 16 + q * 2];
        float4 zr1 = ((const float4*)G_ZR)[(size_t)node * 16 + q * 2 + 1];
        float4 b0 = __ldg(&((const float4*)b)[q * 2]);
        float4 b1 = __ldg(&((const float4*)b)[q * 2 + 1]);
        h0.x = a[0] * inv + b0.x + zr0.x;
        h0.y = a[1] * inv + b0.y + zr0.y;
        h0.z = a[2] * inv + b0.z + zr0.z;
        h0.w = a[3] * inv + b0.w + zr0.w;
        h1.x = a[4] * inv + b1.x + zr1.x;
        h1.y = a[5] * inv + b1.y + zr1.y;
        h1.z = a[6] * inv + b1.z + zr1.z;
        h1.w = a[7] * inv + b1.w + zr1.w;
        if (!FUSE_POOL) {
            ((float4*)G_H)[(size_t)node * 16 + q * 2]     = h0;
            ((float4*)G_H)[(size_t)node * 16 + q * 2 + 1] = h1;
        }
    }

    if (FUSE_POOL) {
        // reduce the block's 8 node-vectors into one per-graph partial
        __shared__ float4 red[8][16];
        if (strm == 0) {
            red[wrp][q * 2]     = h0;
            red[wrp][q * 2 + 1] = h1;
        }
        __syncthreads();
        if (threadIdx.x < 64) {
            const int qq = threadIdx.x >> 2, comp = threadIdx.x & 3;
            float sum = 0.f;
#pragma unroll
            for (int w = 0; w < 8; w++) {
                float4 v = red[w][qq];
                sum += (comp == 0) ? v.x : (comp == 1) ? v.y : (comp == 2) ? v.z : v.w;
            }
            const int g = (blockIdx.x * 8) / NODES_PER_GRAPH;
            atomicAdd(&g_pool[g * D_EMB + qq * 4 + comp], sum);
        }
    }
}

// ================== MLP head =================================================
__global__ void head_kernel(const float* __restrict__ fc1_W,
                            const float* __restrict__ fc1_b,
                            const float* __restrict__ fc2_W,
                            const float* __restrict__ fc2_b,
                            float* __restrict__ out) {
    __shared__ float gs[D_EMB];
    __shared__ float hs[D_HID];
    const int g = blockIdx.x, tid = threadIdx.x;
    if (tid < D_EMB) gs[tid] = g_pool[g * D_EMB + tid] * (1.0f / NODES_PER_GRAPH);
    __syncthreads();
    if (tid < D_HID) {
        float acc = fc1_b[tid];
        const float* w = fc1_W + (size_t)tid * D_EMB;
#pragma unroll
        for (int k = 0; k < D_EMB; k++) acc += gs[k] * w[k];
        hs[tid] = fmaxf(acc, 0.f);
    }
    __syncthreads();
    for (int a = tid; a < N_ACT; a += 256) {
        const float4* w = (const float4*)(fc2_W + (size_t)a * D_HID);
        float a0 = 0.f, a1 = 0.f, a2 = 0.f, a3 = 0.f;
#pragma unroll
        for (int k = 0; k < D_HID / 4; k++) {
            float4 wv = __ldg(&w[k]);
            a0 += wv.x * hs[4 * k + 0];
            a1 += wv.y * hs[4 * k + 1];
            a2 += wv.z * hs[4 * k + 2];
            a3 += wv.w * hs[4 * k + 3];
        }
        out[(size_t)g * N_ACT + a] = fc2_b[a] + (a0 + a1) + (a2 + a3);
    }
}

// ================== launch ===================================================
extern "C" void kernel_launch(void* const* d_in, const int* in_sizes, int n_in,
                              void* d_out, int out_size) {
    const float* x     = (const float*)d_in[0];
    const int*   ei    = (const int*)d_in[1];
    const float* W1l   = (const float*)d_in[2];
    const float* b1l   = (const float*)d_in[3];
    const float* W1r   = (const float*)d_in[4];
    const float* W2l   = (const float*)d_in[5];
    const float* b2l   = (const float*)d_in[6];
    const float* W2r   = (const float*)d_in[7];
    const float* fc1_W = (const float*)d_in[8];
    const float* fc1_b = (const float*)d_in[9];
    const float* fc2_W = (const float*)d_in[10];
    const float* fc2_b = (const float*)d_in[11];
    float* out = (float*)d_out;

    const int* src = ei;
    const int* dst = ei + N_EDGES;

    const int SMEM1 = 2 * 128 * (D_IN / 2 + 4) * 4;   // 69632 B
    const int SMEM2 = 2 * 128 * (D_EMB / 2 + 4) * 4;  // 36864 B
    cudaFuncSetAttribute(lin_tc_kernel<D_IN>,  cudaFuncAttributeMaxDynamicSharedMemorySize, SMEM1);
    cudaFuncSetAttribute(lin_tc_kernel<D_EMB>, cudaFuncAttributeMaxDynamicSharedMemorySize, SMEM2);

    init_kernel<<<N_NODES / 256, 256>>>(W1l, W1r, W2l, W2r);
    hist_kernel<<<2048, 256>>>(dst);
    alloc_kernel<<<N_NODES / 256, 256>>>();
    scatter_kernel<<<2048, 256>>>(src, dst);      // profiler slot #4 (control)

    lin_tc_kernel<D_IN><<<N_NODES / 128, 256, SMEM1>>>(x);
    gather_h_kernel<false><<<N_NODES / 8, 256>>>(b1l);

    lin_tc_kernel<D_EMB><<<N_NODES / 128, 256, SMEM2>>>(nullptr);
    gather_h_kernel<true><<<N_NODES / 8, 256>>>(b2l);

    head_kernel<<<N_GRAPHS, 256>>>(fc1_W, fc1_b, fc2_W, fc2_b, out);
}